// round 6
// baseline (speedup 1.0000x reference)
#include <cuda_runtime.h>
#include <math.h>

#define NPIX  131072            // B*H*W = 2*256*256
#define HW    65536
#define EPSF  1e-6f

// ---------------- scratch (static __device__, no allocation) ----------------
__device__ float4 g4_short[NPIX * 4];
__device__ float4 g4_feat0[NPIX * 4];
__device__ float4 g4_n1[NPIX * 4];
__device__ float4 g4_a1[NPIX * 4];
__device__ float4 g4_feat[NPIX * 4];
__device__ float4 g_sig[NPIX];             // (sx, sy, sr, -)

// ---------------- helpers ----------------
__device__ __forceinline__ float4 f4fma(float a, float4 b, float4 c) {
    return make_float4(fmaf(a, b.x, c.x), fmaf(a, b.y, c.y),
                       fmaf(a, b.z, c.z), fmaf(a, b.w, c.w));
}
__device__ __forceinline__ float4 f4scale(float a, float4 b) {
    return make_float4(a * b.x, a * b.y, a * b.z, a * b.w);
}
__device__ __forceinline__ float4 f4add(float4 a, float4 b) {
    return make_float4(a.x + b.x, a.y + b.y, a.z + b.z, a.w + b.w);
}
__device__ __forceinline__ float dot44(float4 a, float4 b) {
    return fmaf(a.x, b.x, fmaf(a.y, b.y, fmaf(a.z, b.z, a.w * b.w)));
}
__device__ __forceinline__ float rsum4(float v) {
    v += __shfl_xor_sync(0xffffffffu, v, 1);
    v += __shfl_xor_sync(0xffffffffu, v, 2);
    return v;
}
__device__ __forceinline__ void bcast16v(float4 v, int lane, float4 out[4]) {
    int base = lane & ~3;
#pragma unroll
    for (int q = 0; q < 4; q++) {
        out[q] = make_float4(__shfl_sync(0xffffffffu, v.x, base + q),
                             __shfl_sync(0xffffffffu, v.y, base + q),
                             __shfl_sync(0xffffffffu, v.z, base + q),
                             __shfl_sync(0xffffffffu, v.w, base + q));
    }
}
__device__ __forceinline__ float geluf(float v) {
    return 0.5f * v * (1.0f + erff(v * 0.7071067811865476f));
}
__device__ __forceinline__ float tanh_p(float x) {
    float ax = fabsf(x);
    float e = __expf(2.0f * ax);
    float t = 1.0f - 2.0f / (e + 1.0f);
    return copysignf(t, x);
}
__device__ __forceinline__ float reflectf(float c) {
    c = fmodf(fabsf(c), 510.0f);
    return c > 255.0f ? 510.0f - c : c;
}
__device__ __forceinline__ int reflecti(int i) {
    i = abs(i);
    return i > 255 ? 510 - i : i;
}
// reflect + floor + clamp + pack indices; returns (idx01,idx23) bits + wx,wy
struct TapPack { unsigned ua, ub; float wx, wy; };
__device__ __forceinline__ TapPack mk_tap_pack(float ix, float iy) {
    ix = reflectf(ix);
    iy = reflectf(iy);
    float fx = floorf(ix), fy = floorf(iy);
    TapPack t;
    t.wx = ix - fx;  t.wy = iy - fy;
    int x0 = (int)fx, y0 = (int)fy;
    int x1 = min(x0 + 1, 255), y1 = min(y0 + 1, 255);
    int r0 = y0 << 8, r1 = y1 << 8;
    t.ua = (unsigned)(r0 + x0) | ((unsigned)(r0 + x1) << 16);
    t.ub = (unsigned)(r1 + x0) | ((unsigned)(r1 + x1) << 16);
    return t;
}

// ---------------- smem loaders ----------------
__device__ __forceinline__ void ldblk(float* dst, const float* src, int n, int tid) {
    for (int i = tid; i < n; i += 128) dst[i] = src[i];
}
__device__ __forceinline__ void ldpad(float* dst, const float* src, int rows, int tid) {
    for (int i = tid; i < rows * 16; i += 128) {
        int r = i >> 4, c = i & 15;
        dst[r * 20 + c] = src[i];
    }
}
__device__ __forceinline__ void ldtpad(float* dst, const float* src, int tid) {
    for (int i = tid; i < 256; i += 128) {
        int o = i >> 4, c = i & 15;
        dst[c * 20 + o] = src[i];
    }
}

// ---------------- K1: proj + gelu + rmsnorm (4 lanes / pixel) ----------------
__global__ void k1_proj(const float* __restrict__ x,
                        const float* __restrict__ pm_w, const float* __restrict__ pm_b,
                        const float* __restrict__ pa_w, const float* __restrict__ pa_b,
                        const float* __restrict__ n1w) {
    int t = blockIdx.x * blockDim.x + threadIdx.x;
    int p = t >> 2, j = t & 3;
    int b = p >> 16;
    int hw = p & 0xFFFF;
    const float* xb = x + (size_t)b * 4 * HW;
    float x0 = xb[hw], x1 = xb[HW + hw], x2 = xb[2 * HW + hw], x3 = xb[3 * HW + hw];

    int c0 = 4 * j;
    float sc[4], f0[4];
    float ssp = 0.0f;
#pragma unroll
    for (int q = 0; q < 4; q++) {
        int c = c0 + q;
        float v = pm_w[c] * x0 + pm_b[c] + pa_b[c]
                + pa_w[c * 3 + 0] * x1 + pa_w[c * 3 + 1] * x2 + pa_w[c * 3 + 2] * x3;
        sc[q] = v;
        float g = geluf(v);
        f0[q] = g;
        ssp += g * g;
    }
    float ss = rsum4(ssp);
    float inv = 1.0f / (sqrtf(ss) * 0.25f + EPSF);

    g4_short[(size_t)p * 4 + j] = make_float4(sc[0], sc[1], sc[2], sc[3]);
    g4_feat0[(size_t)p * 4 + j] = make_float4(f0[0], f0[1], f0[2], f0[3]);
    g4_n1[(size_t)p * 4 + j] = make_float4(f0[0] * inv * n1w[c0],
                                           f0[1] * inv * n1w[c0 + 1],
                                           f0[2] * inv * n1w[c0 + 2],
                                           f0[3] * inv * n1w[c0 + 3]);
}

// ---------------- deform core: taps finished in phase 1 ----------------
// tap_s[k] = (idx01 bits, idx23 bits, wx, omy*e); aux_s[k] = wy*e
__device__ __forceinline__ float4 deform_core4(
    const float4* __restrict__ sb, int y, int x, int lane, int j,
    const float* s_dww, const float* s_dwb,
    const float4* s_pw4, const float* s_pwb,
    float spacing, float mo, float4* tap_s, float* aux_s)
{
    const int c0 = 4 * j;

    // depthwise 3x3 (reflect) + bias, channel-split
    float4 h = make_float4(s_dwb[c0], s_dwb[c0 + 1], s_dwb[c0 + 2], s_dwb[c0 + 3]);
#pragma unroll
    for (int ky = 0; ky < 3; ky++) {
        int yy = reflecti(y + ky - 1);
#pragma unroll
        for (int kx = 0; kx < 3; kx++) {
            int xx = reflecti(x + kx - 1);
            float4 v = sb[(((yy << 8) + xx) << 2) + j];
            const float* wb = s_dww + ky * 3 + kx;
            h.x = fmaf(v.x, wb[(c0 + 0) * 9], h.x);
            h.y = fmaf(v.y, wb[(c0 + 1) * 9], h.y);
            h.z = fmaf(v.z, wb[(c0 + 2) * 9], h.z);
            h.w = fmaf(v.w, wb[(c0 + 3) * 9], h.w);
        }
    }
    h.x = geluf(h.x); h.y = geluf(h.y); h.z = geluf(h.z); h.w = geluf(h.w);

    float4 hv[4];
    bcast16v(h, lane, hv);

    // phase 1: lane j owns k = j, j+4, ... -> full tap construction
    for (int k = j; k < 25; k += 4) {
        const float4* wx4 = s_pw4 + (2 * k) * 5;
        const float4* wy4 = s_pw4 + (2 * k + 1) * 5;
        const float4* wl4 = s_pw4 + (50 + k) * 5;
        float px = s_pwb[2 * k], py = s_pwb[2 * k + 1], pl = s_pwb[50 + k];
#pragma unroll
        for (int q = 0; q < 4; q++) {
            px += dot44(hv[q], wx4[q]);
            py += dot44(hv[q], wy4[q]);
            pl += dot44(hv[q], wl4[q]);
        }
        float dx = spacing * (float)((k % 5) - 2) + tanh_p(px) * mo;
        float dy = spacing * (float)((k / 5) - 2) + tanh_p(py) * mo;
        float e = __expf(pl);
        TapPack tp = mk_tap_pack((float)x + dx, (float)y + dy);
        tap_s[k] = make_float4(__uint_as_float(tp.ua), __uint_as_float(tp.ub),
                               tp.wx, (1.0f - tp.wy) * e);
        aux_s[k] = tp.wy * e;
    }
    __syncwarp();

    // phase 2: pure gather
    float4 acc = make_float4(0.f, 0.f, 0.f, 0.f);
    float den = 0.0f;
#pragma unroll 2
    for (int k = 0; k < 25; k++) {
        float4 tp = tap_s[k];
        float wye = aux_s[k];
        unsigned ua = __float_as_uint(tp.x), ub = __float_as_uint(tp.y);
        int i00 = ua & 0xffff, i01 = ua >> 16, i10 = ub & 0xffff, i11 = ub >> 16;
        float wx = tp.z, omye = tp.w;
        float omx = 1.0f - wx;
        acc = f4fma(omx * omye, sb[(i00 << 2) + j], acc);
        acc = f4fma(wx * omye,  sb[(i01 << 2) + j], acc);
        acc = f4fma(omx * wye,  sb[(i10 << 2) + j], acc);
        acc = f4fma(wx * wye,   sb[(i11 << 2) + j], acc);
        den += omye + wye;
    }
    return f4scale(1.0f / den, acc);
}

// ---------------- K2: fine deform  (n1 -> a1) ----------------
__global__ void __launch_bounds__(128)
k2_fine(const float* __restrict__ dww, const float* __restrict__ dwb,
        const float* __restrict__ pww, const float* __restrict__ pwb) {
    __shared__ float s_dww[144], s_dwb[16], s_pwb[75];
    __shared__ float4 s_pw4[75 * 5];
    __shared__ float4 s_tap[32][25];
    __shared__ float s_aux[32][25];
    int tid = threadIdx.x;
    ldblk(s_dww, dww, 144, tid);
    ldblk(s_dwb, dwb, 16, tid);
    ldblk(s_pwb, pwb, 75, tid);
    ldpad((float*)s_pw4, pww, 75, tid);
    __syncthreads();

    int t = blockIdx.x * blockDim.x + tid;
    int p = t >> 2, j = t & 3;
    int lane = tid & 31;
    int g = tid >> 2;
    int b = p >> 16, y = (p >> 8) & 255, x = p & 255;
    const float4* sb = g4_n1 + ((size_t)b << 18);
    g4_a1[(size_t)p * 4 + j] =
        deform_core4(sb, y, x, lane, j, s_dww, s_dwb, s_pw4, s_pwb,
                     1.0f, 4.0f, &s_tap[g][0], &s_aux[g][0]);
}

// ---------------- K3: coarse deform + rmsnorm + gate + proj_out + sigma ----------------
__global__ void __launch_bounds__(128)
k3_coarse_tail(const float* __restrict__ dww, const float* __restrict__ dwb,
               const float* __restrict__ pww, const float* __restrict__ pwb,
               const float* __restrict__ n2w,
               const float* __restrict__ gate_w, const float* __restrict__ gate_b,
               const float* __restrict__ pout_w, const float* __restrict__ pout_b,
               const float* __restrict__ sig_w, const float* __restrict__ sig_b) {
    __shared__ float s_dww[144], s_dwb[16], s_pwb[75], s_n2w[16], s_sigb[3];
    __shared__ float4 s_pw4[75 * 5];
    __shared__ float4 s_gT4[16 * 5], s_pT4[16 * 5];
    __shared__ float4 s_gb4[4], s_pb4[4], s_sig4[12];
    __shared__ float4 s_tap[32][25];
    __shared__ float s_aux[32][25];
    int tid = threadIdx.x;
    ldblk(s_dww, dww, 144, tid);
    ldblk(s_dwb, dwb, 16, tid);
    ldblk(s_pwb, pwb, 75, tid);
    ldpad((float*)s_pw4, pww, 75, tid);
    ldtpad((float*)s_gT4, gate_w, tid);
    ldtpad((float*)s_pT4, pout_w, tid);
    ldblk((float*)s_gb4, gate_b, 16, tid);
    ldblk((float*)s_pb4, pout_b, 16, tid);
    ldblk((float*)s_sig4, sig_w, 48, tid);
    ldblk(s_n2w, n2w, 16, tid);
    ldblk(s_sigb, sig_b, 3, tid);
    __syncthreads();

    int t = blockIdx.x * blockDim.x + tid;
    int p = t >> 2, j = t & 3;
    int lane = tid & 31;
    int g = tid >> 2;
    int b = p >> 16, y = (p >> 8) & 255, x = p & 255;
    const int c0 = 4 * j;
    const float4* sb = g4_a1 + ((size_t)b << 18);

    float4 av = deform_core4(sb, y, x, lane, j, s_dww, s_dwb, s_pw4, s_pwb,
                             3.0f, 6.0f, &s_tap[g][0], &s_aux[g][0]);

    // rmsnorm(a2, norm2)
    float ssp = av.x * av.x + av.y * av.y + av.z * av.z + av.w * av.w;
    float ss = rsum4(ssp);
    float inv = 1.0f / (sqrtf(ss) * 0.25f + EPSF);
    float4 tv = make_float4(av.x * inv * s_n2w[c0], av.y * inv * s_n2w[c0 + 1],
                            av.z * inv * s_n2w[c0 + 2], av.w * inv * s_n2w[c0 + 3]);

    float4 tf[4];
    bcast16v(tv, lane, tf);

    float4 a3 = s_gb4[j];
#pragma unroll
    for (int r = 0; r < 4; r++) {
        a3 = f4fma(tf[r].x, s_gT4[(4 * r + 0) * 5 + j], a3);
        a3 = f4fma(tf[r].y, s_gT4[(4 * r + 1) * 5 + j], a3);
        a3 = f4fma(tf[r].z, s_gT4[(4 * r + 2) * 5 + j], a3);
        a3 = f4fma(tf[r].w, s_gT4[(4 * r + 3) * 5 + j], a3);
    }
    float4 f0v = g4_feat0[(size_t)p * 4 + j];
    float4 gv = make_float4(f0v.x * a3.x, f0v.y * a3.y, f0v.z * a3.z, f0v.w * a3.w);

    float4 gf[4];
    bcast16v(gv, lane, gf);

    float4 fv = f4add(s_pb4[j], g4_short[(size_t)p * 4 + j]);
#pragma unroll
    for (int r = 0; r < 4; r++) {
        fv = f4fma(gf[r].x, s_pT4[(4 * r + 0) * 5 + j], fv);
        fv = f4fma(gf[r].y, s_pT4[(4 * r + 1) * 5 + j], fv);
        fv = f4fma(gf[r].z, s_pT4[(4 * r + 2) * 5 + j], fv);
        fv = f4fma(gf[r].w, s_pT4[(4 * r + 3) * 5 + j], fv);
    }
    g4_feat[(size_t)p * 4 + j] = fv;

    float sg[3];
#pragma unroll
    for (int r = 0; r < 3; r++) {
        float zp = dot44(fv, s_sig4[r * 4 + j]);
        float z = rsum4(zp) + s_sigb[r];
        float sp = fmaxf(z, 0.0f) + log1pf(expf(-fabsf(z)));
        sg[r] = fminf(sp, 6.0f) + EPSF;
    }
    if (j == 0) g_sig[p] = make_float4(sg[0], sg[1], sg[2], 0.0f);
}

// ---------------- K4: joint bilateral ----------------
__global__ void __launch_bounds__(128)
k4_bilateral(const float* __restrict__ xin,
             const float* __restrict__ offw, const float* __restrict__ offb,
             float* __restrict__ out) {
    __shared__ float4 s_ow4[50 * 5];
    __shared__ float s_ob[50];
    __shared__ float4 s_tap[32][25];
    __shared__ float2 s_aux[32][25];   // (spat, patch)
    int tid = threadIdx.x;
    ldpad((float*)s_ow4, offw, 50, tid);
    ldblk(s_ob, offb, 50, tid);
    __syncthreads();

    int t = blockIdx.x * blockDim.x + tid;
    int p = t >> 2, j = t & 3;
    int lane = tid & 31;
    int g = tid >> 2;
    int b = p >> 16, y = (p >> 8) & 255, x = p & 255;

    float4 fv = g4_feat[(size_t)p * 4 + j];
    float4 fvv[4];
    bcast16v(fv, lane, fvv);

    float4 s4 = g_sig[p];
    float axc = 0.5f / (s4.x * s4.x);
    float ayc = 0.5f / (s4.y * s4.y);
    float arc = 0.5f / (s4.z * s4.z);

    const float* plane = xin + (size_t)b * 4 * HW;
    const float4* fb = g4_feat + ((size_t)b << 18);
    float4* tap_s = &s_tap[g][0];
    float2* aux_s = &s_aux[g][0];

    // phase 1: lane j owns k = j, j+4, ... -> tap + spat + patch
    for (int k = j; k < 25; k += 4) {
        const float4* wx4 = s_ow4 + (2 * k) * 5;
        const float4* wy4 = s_ow4 + (2 * k + 1) * 5;
        float px = s_ob[2 * k], py = s_ob[2 * k + 1];
#pragma unroll
        for (int q = 0; q < 4; q++) {
            px += dot44(fvv[q], wx4[q]);
            py += dot44(fvv[q], wy4[q]);
        }
        float dx = (float)((k % 5) - 2) + tanh_p(px) * 5.0f;
        float dy = (float)((k / 5) - 2) + tanh_p(py) * 5.0f;
        float spat = dx * dx * axc + dy * dy * ayc;
        TapPack tp = mk_tap_pack((float)x + dx, (float)y + dy);
        int i00 = tp.ua & 0xffff, i01 = tp.ua >> 16;
        int i10 = tp.ub & 0xffff, i11 = tp.ub >> 16;
        float omx = 1.0f - tp.wx, omy = 1.0f - tp.wy;
        float patch = omx * omy * plane[i00] + tp.wx * omy * plane[i01]
                    + omx * tp.wy * plane[i10] + tp.wx * tp.wy * plane[i11];
        tap_s[k] = make_float4(__uint_as_float(tp.ua), __uint_as_float(tp.ub),
                               tp.wx, tp.wy);
        aux_s[k] = make_float2(spat, patch);
    }
    __syncwarp();

    // phase 2: feat gather + range weight
    float num = 0.0f, den = 0.0f;
#pragma unroll 2
    for (int k = 0; k < 25; k++) {
        float4 tp = tap_s[k];
        float2 ax2 = aux_s[k];
        unsigned ua = __float_as_uint(tp.x), ub = __float_as_uint(tp.y);
        int i00 = ua & 0xffff, i01 = ua >> 16, i10 = ub & 0xffff, i11 = ub >> 16;
        float wx = tp.z, wy = tp.w;
        float omx = 1.0f - wx, omy = 1.0f - wy;

        float4 s = f4scale(omx * omy, fb[(i00 << 2) + j]);
        s = f4fma(wx * omy, fb[(i01 << 2) + j], s);
        s = f4fma(omx * wy, fb[(i10 << 2) + j], s);
        s = f4fma(wx * wy,  fb[(i11 << 2) + j], s);
        float ddx = fv.x - s.x, ddy = fv.y - s.y, ddz = fv.z - s.z, ddw = fv.w - s.w;
        float fdp = ddx * ddx + ddy * ddy + ddz * ddz + ddw * ddw;
        float fd = rsum4(fdp);

        float w = __expf(-ax2.x - fd * arc);
        num = fmaf(ax2.y, w, num);
        den += w;
    }
    if (j == 0) out[p] = num / (den + 1e-8f);
}

// ---------------- launch ----------------
extern "C" void kernel_launch(void* const* d_in, const int* in_sizes, int n_in,
                              void* d_out, int out_size) {
    const float* x = (const float*)d_in[0];
    const int TB = 128;
    const int NB4 = (NPIX * 4) / TB;   // 4 lanes per pixel

    k1_proj<<<NB4, TB>>>(x, (const float*)d_in[1], (const float*)d_in[2],
                         (const float*)d_in[3], (const float*)d_in[4],
                         (const float*)d_in[5]);
    k2_fine<<<NB4, TB>>>((const float*)d_in[6], (const float*)d_in[7],
                         (const float*)d_in[8], (const float*)d_in[9]);
    k3_coarse_tail<<<NB4, TB>>>((const float*)d_in[10], (const float*)d_in[11],
                                (const float*)d_in[12], (const float*)d_in[13],
                                (const float*)d_in[14],
                                (const float*)d_in[15], (const float*)d_in[16],
                                (const float*)d_in[17], (const float*)d_in[18],
                                (const float*)d_in[19], (const float*)d_in[20]);
    k4_bilateral<<<NB4, TB>>>(x, (const float*)d_in[21], (const float*)d_in[22],
                              (float*)d_out);
}

// round 7
// speedup vs baseline: 1.1709x; 1.1709x over previous
#include <cuda_runtime.h>
#include <cuda_fp16.h>
#include <math.h>

#define NPIX  131072            // B*H*W = 2*256*256
#define HW    65536
#define EPSF  1e-6f

// ---------------- scratch (static __device__, no allocation) ----------------
__device__ float4 g4_short[NPIX * 4];
__device__ float4 g4_feat0[NPIX * 4];
__device__ float4 g4_feat[NPIX * 4];       // fp32 feat (center reads in k4)
__device__ uint2  gh_n1[NPIX * 4];         // half x4 per lane chunk
__device__ uint2  gh_a1[NPIX * 4];
__device__ uint2  gh_feat[NPIX * 4];
__device__ float4 g_sig[NPIX];             // (sx, sy, sr, -)

// ---------------- helpers ----------------
__device__ __forceinline__ float4 f4fma(float a, float4 b, float4 c) {
    return make_float4(fmaf(a, b.x, c.x), fmaf(a, b.y, c.y),
                       fmaf(a, b.z, c.z), fmaf(a, b.w, c.w));
}
__device__ __forceinline__ float4 f4scale(float a, float4 b) {
    return make_float4(a * b.x, a * b.y, a * b.z, a * b.w);
}
__device__ __forceinline__ float4 f4add(float4 a, float4 b) {
    return make_float4(a.x + b.x, a.y + b.y, a.z + b.z, a.w + b.w);
}
__device__ __forceinline__ float dot44(float4 a, float4 b) {
    return fmaf(a.x, b.x, fmaf(a.y, b.y, fmaf(a.z, b.z, a.w * b.w)));
}
__device__ __forceinline__ float rsum4(float v) {
    v += __shfl_xor_sync(0xffffffffu, v, 1);
    v += __shfl_xor_sync(0xffffffffu, v, 2);
    return v;
}
__device__ __forceinline__ void bcast16v(float4 v, int lane, float4 out[4]) {
    int base = lane & ~3;
#pragma unroll
    for (int q = 0; q < 4; q++) {
        out[q] = make_float4(__shfl_sync(0xffffffffu, v.x, base + q),
                             __shfl_sync(0xffffffffu, v.y, base + q),
                             __shfl_sync(0xffffffffu, v.z, base + q),
                             __shfl_sync(0xffffffffu, v.w, base + q));
    }
}
__device__ __forceinline__ float4 h4tof4(uint2 u) {
    __half2 h0 = *reinterpret_cast<__half2*>(&u.x);
    __half2 h1 = *reinterpret_cast<__half2*>(&u.y);
    float2 a = __half22float2(h0), b = __half22float2(h1);
    return make_float4(a.x, a.y, b.x, b.y);
}
__device__ __forceinline__ uint2 f4toh4(float4 v) {
    __half2 h0 = __floats2half2_rn(v.x, v.y);
    __half2 h1 = __floats2half2_rn(v.z, v.w);
    uint2 u;
    u.x = *reinterpret_cast<unsigned*>(&h0);
    u.y = *reinterpret_cast<unsigned*>(&h1);
    return u;
}
__device__ __forceinline__ float geluf(float v) {
    return 0.5f * v * (1.0f + erff(v * 0.7071067811865476f));
}
__device__ __forceinline__ float tanh_p(float x) {
    float ax = fabsf(x);
    float e = __expf(2.0f * ax);
    float t = 1.0f - 2.0f / (e + 1.0f);
    return copysignf(t, x);
}
__device__ __forceinline__ float reflectf(float c) {
    c = fmodf(fabsf(c), 510.0f);
    return c > 255.0f ? 510.0f - c : c;
}
__device__ __forceinline__ int reflecti(int i) {
    i = abs(i);
    return i > 255 ? 510 - i : i;
}
struct TapPack { unsigned ua, ub; float wx, wy; };
__device__ __forceinline__ TapPack mk_tap_pack(float ix, float iy) {
    ix = reflectf(ix);
    iy = reflectf(iy);
    float fx = floorf(ix), fy = floorf(iy);
    TapPack t;
    t.wx = ix - fx;  t.wy = iy - fy;
    int x0 = (int)fx, y0 = (int)fy;
    int x1 = min(x0 + 1, 255), y1 = min(y0 + 1, 255);
    int r0 = y0 << 8, r1 = y1 << 8;
    t.ua = (unsigned)(r0 + x0) | ((unsigned)(r0 + x1) << 16);
    t.ub = (unsigned)(r1 + x0) | ((unsigned)(r1 + x1) << 16);
    return t;
}

// ---------------- smem loaders ----------------
__device__ __forceinline__ void ldblk(float* dst, const float* src, int n, int tid) {
    for (int i = tid; i < n; i += 128) dst[i] = src[i];
}
__device__ __forceinline__ void ldpad(float* dst, const float* src, int rows, int tid) {
    for (int i = tid; i < rows * 16; i += 128) {
        int r = i >> 4, c = i & 15;
        dst[r * 20 + c] = src[i];
    }
}
__device__ __forceinline__ void ldtpad(float* dst, const float* src, int tid) {
    for (int i = tid; i < 256; i += 128) {
        int o = i >> 4, c = i & 15;
        dst[c * 20 + o] = src[i];
    }
}

// ---------------- K1: proj + gelu + rmsnorm (4 lanes / pixel) ----------------
__global__ void k1_proj(const float* __restrict__ x,
                        const float* __restrict__ pm_w, const float* __restrict__ pm_b,
                        const float* __restrict__ pa_w, const float* __restrict__ pa_b,
                        const float* __restrict__ n1w) {
    int t = blockIdx.x * blockDim.x + threadIdx.x;
    int p = t >> 2, j = t & 3;
    int b = p >> 16;
    int hw = p & 0xFFFF;
    const float* xb = x + (size_t)b * 4 * HW;
    float x0 = xb[hw], x1 = xb[HW + hw], x2 = xb[2 * HW + hw], x3 = xb[3 * HW + hw];

    int c0 = 4 * j;
    float sc[4], f0[4];
    float ssp = 0.0f;
#pragma unroll
    for (int q = 0; q < 4; q++) {
        int c = c0 + q;
        float v = pm_w[c] * x0 + pm_b[c] + pa_b[c]
                + pa_w[c * 3 + 0] * x1 + pa_w[c * 3 + 1] * x2 + pa_w[c * 3 + 2] * x3;
        sc[q] = v;
        float g = geluf(v);
        f0[q] = g;
        ssp += g * g;
    }
    float ss = rsum4(ssp);
    float inv = 1.0f / (sqrtf(ss) * 0.25f + EPSF);

    g4_short[(size_t)p * 4 + j] = make_float4(sc[0], sc[1], sc[2], sc[3]);
    g4_feat0[(size_t)p * 4 + j] = make_float4(f0[0], f0[1], f0[2], f0[3]);
    gh_n1[(size_t)p * 4 + j] = f4toh4(make_float4(f0[0] * inv * n1w[c0],
                                                  f0[1] * inv * n1w[c0 + 1],
                                                  f0[2] * inv * n1w[c0 + 2],
                                                  f0[3] * inv * n1w[c0 + 3]));
}

// ---------------- deform core: half-gather, taps finished in phase 1 ----------
__device__ __forceinline__ float4 deform_core4(
    const uint2* __restrict__ sb, int y, int x, int lane, int j,
    const float* s_dww, const float* s_dwb,
    const float4* s_pw4, const float* s_pwb,
    float spacing, float mo, float4* tap_s, float* aux_s)
{
    const int c0 = 4 * j;

    // depthwise 3x3 (reflect) + bias, channel-split
    float4 h = make_float4(s_dwb[c0], s_dwb[c0 + 1], s_dwb[c0 + 2], s_dwb[c0 + 3]);
#pragma unroll
    for (int ky = 0; ky < 3; ky++) {
        int yy = reflecti(y + ky - 1);
#pragma unroll
        for (int kx = 0; kx < 3; kx++) {
            int xx = reflecti(x + kx - 1);
            float4 v = h4tof4(sb[(((yy << 8) + xx) << 2) + j]);
            const float* wb = s_dww + ky * 3 + kx;
            h.x = fmaf(v.x, wb[(c0 + 0) * 9], h.x);
            h.y = fmaf(v.y, wb[(c0 + 1) * 9], h.y);
            h.z = fmaf(v.z, wb[(c0 + 2) * 9], h.z);
            h.w = fmaf(v.w, wb[(c0 + 3) * 9], h.w);
        }
    }
    h.x = geluf(h.x); h.y = geluf(h.y); h.z = geluf(h.z); h.w = geluf(h.w);

    float4 hv[4];
    bcast16v(h, lane, hv);

    // phase 1: lane j owns k = j, j+4, ...
    for (int k = j; k < 25; k += 4) {
        const float4* wx4 = s_pw4 + (2 * k) * 5;
        const float4* wy4 = s_pw4 + (2 * k + 1) * 5;
        const float4* wl4 = s_pw4 + (50 + k) * 5;
        float px = s_pwb[2 * k], py = s_pwb[2 * k + 1], pl = s_pwb[50 + k];
#pragma unroll
        for (int q = 0; q < 4; q++) {
            px += dot44(hv[q], wx4[q]);
            py += dot44(hv[q], wy4[q]);
            pl += dot44(hv[q], wl4[q]);
        }
        float dx = spacing * (float)((k % 5) - 2) + tanh_p(px) * mo;
        float dy = spacing * (float)((k / 5) - 2) + tanh_p(py) * mo;
        float e = __expf(pl);
        TapPack tp = mk_tap_pack((float)x + dx, (float)y + dy);
        tap_s[k] = make_float4(__uint_as_float(tp.ua), __uint_as_float(tp.ub),
                               tp.wx, (1.0f - tp.wy) * e);
        aux_s[k] = tp.wy * e;
    }
    __syncwarp();

    // phase 2: pure gather (half loads)
    float4 acc = make_float4(0.f, 0.f, 0.f, 0.f);
    float den = 0.0f;
#pragma unroll 2
    for (int k = 0; k < 25; k++) {
        float4 tp = tap_s[k];
        float wye = aux_s[k];
        unsigned ua = __float_as_uint(tp.x), ub = __float_as_uint(tp.y);
        int i00 = ua & 0xffff, i01 = ua >> 16, i10 = ub & 0xffff, i11 = ub >> 16;
        float wx = tp.z, omye = tp.w;
        float omx = 1.0f - wx;
        acc = f4fma(omx * omye, h4tof4(sb[(i00 << 2) + j]), acc);
        acc = f4fma(wx * omye,  h4tof4(sb[(i01 << 2) + j]), acc);
        acc = f4fma(omx * wye,  h4tof4(sb[(i10 << 2) + j]), acc);
        acc = f4fma(wx * wye,   h4tof4(sb[(i11 << 2) + j]), acc);
        den += omye + wye;
    }
    return f4scale(1.0f / den, acc);
}

// ---------------- K2: fine deform  (n1 -> a1) ----------------
__global__ void __launch_bounds__(128)
k2_fine(const float* __restrict__ dww, const float* __restrict__ dwb,
        const float* __restrict__ pww, const float* __restrict__ pwb) {
    __shared__ float s_dww[144], s_dwb[16], s_pwb[75];
    __shared__ float4 s_pw4[75 * 5];
    __shared__ float4 s_tap[32][25];
    __shared__ float s_aux[32][25];
    int tid = threadIdx.x;
    ldblk(s_dww, dww, 144, tid);
    ldblk(s_dwb, dwb, 16, tid);
    ldblk(s_pwb, pwb, 75, tid);
    ldpad((float*)s_pw4, pww, 75, tid);
    __syncthreads();

    int t = blockIdx.x * blockDim.x + tid;
    int p = t >> 2, j = t & 3;
    int lane = tid & 31;
    int g = tid >> 2;
    int b = p >> 16, y = (p >> 8) & 255, x = p & 255;
    const uint2* sb = gh_n1 + ((size_t)b << 18);
    float4 o = deform_core4(sb, y, x, lane, j, s_dww, s_dwb, s_pw4, s_pwb,
                            1.0f, 4.0f, &s_tap[g][0], &s_aux[g][0]);
    gh_a1[(size_t)p * 4 + j] = f4toh4(o);
}

// ---------------- K3: coarse deform + rmsnorm + gate + proj_out + sigma ----------------
__global__ void __launch_bounds__(128)
k3_coarse_tail(const float* __restrict__ dww, const float* __restrict__ dwb,
               const float* __restrict__ pww, const float* __restrict__ pwb,
               const float* __restrict__ n2w,
               const float* __restrict__ gate_w, const float* __restrict__ gate_b,
               const float* __restrict__ pout_w, const float* __restrict__ pout_b,
               const float* __restrict__ sig_w, const float* __restrict__ sig_b) {
    __shared__ float s_dww[144], s_dwb[16], s_pwb[75], s_n2w[16], s_sigb[3];
    __shared__ float4 s_pw4[75 * 5];
    __shared__ float4 s_gT4[16 * 5], s_pT4[16 * 5];
    __shared__ float4 s_gb4[4], s_pb4[4], s_sig4[12];
    __shared__ float4 s_tap[32][25];
    __shared__ float s_aux[32][25];
    int tid = threadIdx.x;
    ldblk(s_dww, dww, 144, tid);
    ldblk(s_dwb, dwb, 16, tid);
    ldblk(s_pwb, pwb, 75, tid);
    ldpad((float*)s_pw4, pww, 75, tid);
    ldtpad((float*)s_gT4, gate_w, tid);
    ldtpad((float*)s_pT4, pout_w, tid);
    ldblk((float*)s_gb4, gate_b, 16, tid);
    ldblk((float*)s_pb4, pout_b, 16, tid);
    ldblk((float*)s_sig4, sig_w, 48, tid);
    ldblk(s_n2w, n2w, 16, tid);
    ldblk(s_sigb, sig_b, 3, tid);
    __syncthreads();

    int t = blockIdx.x * blockDim.x + tid;
    int p = t >> 2, j = t & 3;
    int lane = tid & 31;
    int g = tid >> 2;
    int b = p >> 16, y = (p >> 8) & 255, x = p & 255;
    const int c0 = 4 * j;
    const uint2* sb = gh_a1 + ((size_t)b << 18);

    float4 av = deform_core4(sb, y, x, lane, j, s_dww, s_dwb, s_pw4, s_pwb,
                             3.0f, 6.0f, &s_tap[g][0], &s_aux[g][0]);

    // rmsnorm(a2, norm2)
    float ssp = av.x * av.x + av.y * av.y + av.z * av.z + av.w * av.w;
    float ss = rsum4(ssp);
    float inv = 1.0f / (sqrtf(ss) * 0.25f + EPSF);
    float4 tv = make_float4(av.x * inv * s_n2w[c0], av.y * inv * s_n2w[c0 + 1],
                            av.z * inv * s_n2w[c0 + 2], av.w * inv * s_n2w[c0 + 3]);

    float4 tf[4];
    bcast16v(tv, lane, tf);

    float4 a3 = s_gb4[j];
#pragma unroll
    for (int r = 0; r < 4; r++) {
        a3 = f4fma(tf[r].x, s_gT4[(4 * r + 0) * 5 + j], a3);
        a3 = f4fma(tf[r].y, s_gT4[(4 * r + 1) * 5 + j], a3);
        a3 = f4fma(tf[r].z, s_gT4[(4 * r + 2) * 5 + j], a3);
        a3 = f4fma(tf[r].w, s_gT4[(4 * r + 3) * 5 + j], a3);
    }
    float4 f0v = g4_feat0[(size_t)p * 4 + j];
    float4 gv = make_float4(f0v.x * a3.x, f0v.y * a3.y, f0v.z * a3.z, f0v.w * a3.w);

    float4 gf[4];
    bcast16v(gv, lane, gf);

    float4 fv = f4add(s_pb4[j], g4_short[(size_t)p * 4 + j]);
#pragma unroll
    for (int r = 0; r < 4; r++) {
        fv = f4fma(gf[r].x, s_pT4[(4 * r + 0) * 5 + j], fv);
        fv = f4fma(gf[r].y, s_pT4[(4 * r + 1) * 5 + j], fv);
        fv = f4fma(gf[r].z, s_pT4[(4 * r + 2) * 5 + j], fv);
        fv = f4fma(gf[r].w, s_pT4[(4 * r + 3) * 5 + j], fv);
    }
    g4_feat[(size_t)p * 4 + j] = fv;
    gh_feat[(size_t)p * 4 + j] = f4toh4(fv);

    float sg[3];
#pragma unroll
    for (int r = 0; r < 3; r++) {
        float zp = dot44(fv, s_sig4[r * 4 + j]);
        float z = rsum4(zp) + s_sigb[r];
        float sp = fmaxf(z, 0.0f) + log1pf(expf(-fabsf(z)));
        sg[r] = fminf(sp, 6.0f) + EPSF;
    }
    if (j == 0) g_sig[p] = make_float4(sg[0], sg[1], sg[2], 0.0f);
}

// ---------------- K4: joint bilateral ----------------
__global__ void __launch_bounds__(128)
k4_bilateral(const float* __restrict__ xin,
             const float* __restrict__ offw, const float* __restrict__ offb,
             float* __restrict__ out) {
    __shared__ float4 s_ow4[50 * 5];
    __shared__ float s_ob[50];
    __shared__ float4 s_tap[32][25];
    __shared__ float s_aux[32][25];   // spat
    int tid = threadIdx.x;
    ldpad((float*)s_ow4, offw, 50, tid);
    ldblk(s_ob, offb, 50, tid);
    __syncthreads();

    int t = blockIdx.x * blockDim.x + tid;
    int p = t >> 2, j = t & 3;
    int lane = tid & 31;
    int g = tid >> 2;
    int b = p >> 16, y = (p >> 8) & 255, x = p & 255;

    float4 fv = g4_feat[(size_t)p * 4 + j];
    float4 fvv[4];
    bcast16v(fv, lane, fvv);

    float4 s4 = g_sig[p];
    float axc = 0.5f / (s4.x * s4.x);
    float ayc = 0.5f / (s4.y * s4.y);
    float arc = 0.5f / (s4.z * s4.z);

    const float* plane = xin + (size_t)b * 4 * HW;
    const uint2* fb = gh_feat + ((size_t)b << 18);
    float4* tap_s = &s_tap[g][0];
    float* aux_s = &s_aux[g][0];

    // phase 1: lane j owns k = j, j+4, ... (compute only, no scattered loads)
    for (int k = j; k < 25; k += 4) {
        const float4* wx4 = s_ow4 + (2 * k) * 5;
        const float4* wy4 = s_ow4 + (2 * k + 1) * 5;
        float px = s_ob[2 * k], py = s_ob[2 * k + 1];
#pragma unroll
        for (int q = 0; q < 4; q++) {
            px += dot44(fvv[q], wx4[q]);
            py += dot44(fvv[q], wy4[q]);
        }
        float dx = (float)((k % 5) - 2) + tanh_p(px) * 5.0f;
        float dy = (float)((k / 5) - 2) + tanh_p(py) * 5.0f;
        float spat = dx * dx * axc + dy * dy * ayc;
        TapPack tp = mk_tap_pack((float)x + dx, (float)y + dy);
        tap_s[k] = make_float4(__uint_as_float(tp.ua), __uint_as_float(tp.ub),
                               tp.wx, tp.wy);
        aux_s[k] = spat;
    }
    __syncwarp();

    // phase 2: feat gather (half) + corner-split patch + range weight
    float num = 0.0f, den = 0.0f;
#pragma unroll 2
    for (int k = 0; k < 25; k++) {
        float4 tp = tap_s[k];
        float spat = aux_s[k];
        unsigned ua = __float_as_uint(tp.x), ub = __float_as_uint(tp.y);
        int i00 = ua & 0xffff, i01 = ua >> 16, i10 = ub & 0xffff, i11 = ub >> 16;
        float wx = tp.z, wy = tp.w;
        float omx = 1.0f - wx, omy = 1.0f - wy;
        float w00 = omx * omy, w01 = wx * omy, w10 = omx * wy, w11 = wx * wy;

        float4 s = f4scale(w00, h4tof4(fb[(i00 << 2) + j]));
        s = f4fma(w01, h4tof4(fb[(i01 << 2) + j]), s);
        s = f4fma(w10, h4tof4(fb[(i10 << 2) + j]), s);
        s = f4fma(w11, h4tof4(fb[(i11 << 2) + j]), s);
        float ddx = fv.x - s.x, ddy = fv.y - s.y, ddz = fv.z - s.z, ddw = fv.w - s.w;
        float fdp = ddx * ddx + ddy * ddy + ddz * ddz + ddw * ddw;

        // patch partial: lane j loads its corner only
        int ci = (j & 2) ? ((j & 1) ? i11 : i10) : ((j & 1) ? i01 : i00);
        float cw = (j & 2) ? ((j & 1) ? w11 : w10) : ((j & 1) ? w01 : w00);
        float pp = cw * plane[ci];

        float fd = rsum4(fdp);
        float patch = rsum4(pp);

        float w = __expf(-spat - fd * arc);
        num = fmaf(patch, w, num);
        den += w;
    }
    if (j == 0) out[p] = num / (den + 1e-8f);
}

// ---------------- launch ----------------
extern "C" void kernel_launch(void* const* d_in, const int* in_sizes, int n_in,
                              void* d_out, int out_size) {
    const float* x = (const float*)d_in[0];
    const int TB = 128;
    const int NB4 = (NPIX * 4) / TB;   // 4 lanes per pixel

    k1_proj<<<NB4, TB>>>(x, (const float*)d_in[1], (const float*)d_in[2],
                         (const float*)d_in[3], (const float*)d_in[4],
                         (const float*)d_in[5]);
    k2_fine<<<NB4, TB>>>((const float*)d_in[6], (const float*)d_in[7],
                         (const float*)d_in[8], (const float*)d_in[9]);
    k3_coarse_tail<<<NB4, TB>>>((const float*)d_in[10], (const float*)d_in[11],
                                (const float*)d_in[12], (const float*)d_in[13],
                                (const float*)d_in[14],
                                (const float*)d_in[15], (const float*)d_in[16],
                                (const float*)d_in[17], (const float*)d_in[18],
                                (const float*)d_in[19], (const float*)d_in[20]);
    k4_bilateral<<<NB4, TB>>>(x, (const float*)d_in[21], (const float*)d_in[22],
                              (float*)d_out);
}

// round 8
// speedup vs baseline: 1.2457x; 1.0639x over previous
#include <cuda_runtime.h>
#include <cuda_fp16.h>
#include <math.h>

#define NPIX  131072            // B*H*W = 2*256*256
#define HW    65536
#define EPSF  1e-6f
#define TB    256

// ---------------- scratch (static __device__, no allocation) ----------------
__device__ float4 g4_short[NPIX * 4];
__device__ float4 g4_feat0[NPIX * 4];
__device__ float4 g4_feat[NPIX * 4];       // fp32 feat (center reads in k4)
__device__ uint2  gh_n1[NPIX * 4];         // half x4 per lane chunk
__device__ uint2  gh_a1[NPIX * 4];
__device__ uint2  gh_feat[NPIX * 4];
__device__ float4 g_sig[NPIX];             // (sx, sy, sr, -)

// ---------------- helpers ----------------
__device__ __forceinline__ float4 f4fma(float a, float4 b, float4 c) {
    return make_float4(fmaf(a, b.x, c.x), fmaf(a, b.y, c.y),
                       fmaf(a, b.z, c.z), fmaf(a, b.w, c.w));
}
__device__ __forceinline__ float4 f4scale(float a, float4 b) {
    return make_float4(a * b.x, a * b.y, a * b.z, a * b.w);
}
__device__ __forceinline__ float4 f4add(float4 a, float4 b) {
    return make_float4(a.x + b.x, a.y + b.y, a.z + b.z, a.w + b.w);
}
__device__ __forceinline__ float dot44(float4 a, float4 b) {
    return fmaf(a.x, b.x, fmaf(a.y, b.y, fmaf(a.z, b.z, a.w * b.w)));
}
__device__ __forceinline__ float rsum4(float v) {
    v += __shfl_xor_sync(0xffffffffu, v, 1);
    v += __shfl_xor_sync(0xffffffffu, v, 2);
    return v;
}
__device__ __forceinline__ void bcast16v(float4 v, int lane, float4 out[4]) {
    int base = lane & ~3;
#pragma unroll
    for (int q = 0; q < 4; q++) {
        out[q] = make_float4(__shfl_sync(0xffffffffu, v.x, base + q),
                             __shfl_sync(0xffffffffu, v.y, base + q),
                             __shfl_sync(0xffffffffu, v.z, base + q),
                             __shfl_sync(0xffffffffu, v.w, base + q));
    }
}
__device__ __forceinline__ float4 h4tof4(uint2 u) {
    __half2 h0 = *reinterpret_cast<__half2*>(&u.x);
    __half2 h1 = *reinterpret_cast<__half2*>(&u.y);
    float2 a = __half22float2(h0), b = __half22float2(h1);
    return make_float4(a.x, a.y, b.x, b.y);
}
__device__ __forceinline__ uint2 f4toh4(float4 v) {
    __half2 h0 = __floats2half2_rn(v.x, v.y);
    __half2 h1 = __floats2half2_rn(v.z, v.w);
    uint2 u;
    u.x = *reinterpret_cast<unsigned*>(&h0);
    u.y = *reinterpret_cast<unsigned*>(&h1);
    return u;
}
__device__ __forceinline__ float geluf(float v) {
    return 0.5f * v * (1.0f + erff(v * 0.7071067811865476f));
}
__device__ __forceinline__ float tanh_p(float x) {
    float ax = fabsf(x);
    float e = __expf(2.0f * ax);
    float t = 1.0f - 2.0f / (e + 1.0f);
    return copysignf(t, x);
}
// valid for |c| < 510 (always true here: |offset| <= 12, x in [0,255])
__device__ __forceinline__ float reflectf(float c) {
    float a = fabsf(c);
    return a > 255.0f ? 510.0f - a : a;
}
__device__ __forceinline__ int reflecti(int i) {
    i = abs(i);
    return i > 255 ? 510 - i : i;
}
struct TapPack { unsigned ua, ub; float wx, wy; };
__device__ __forceinline__ TapPack mk_tap_pack(float ix, float iy) {
    ix = reflectf(ix);
    iy = reflectf(iy);
    float fx = floorf(ix), fy = floorf(iy);
    TapPack t;
    t.wx = ix - fx;  t.wy = iy - fy;
    int x0 = (int)fx, y0 = (int)fy;
    int x1 = min(x0 + 1, 255), y1 = min(y0 + 1, 255);
    int r0 = y0 << 8, r1 = y1 << 8;
    t.ua = (unsigned)(r0 + x0) | ((unsigned)(r0 + x1) << 16);
    t.ub = (unsigned)(r1 + x0) | ((unsigned)(r1 + x1) << 16);
    return t;
}

// ---------------- smem loaders (TB threads) ----------------
__device__ __forceinline__ void ldblk(float* dst, const float* src, int n, int tid) {
    for (int i = tid; i < n; i += TB) dst[i] = src[i];
}
__device__ __forceinline__ void ldpad(float* dst, const float* src, int rows, int tid) {
    for (int i = tid; i < rows * 16; i += TB) {
        int r = i >> 4, c = i & 15;
        dst[r * 20 + c] = src[i];
    }
}
__device__ __forceinline__ void ldtpad(float* dst, const float* src, int tid) {
    for (int i = tid; i < 256; i += TB) {
        int o = i >> 4, c = i & 15;
        dst[c * 20 + o] = src[i];
    }
}

// ---------------- K1: proj + gelu + rmsnorm (4 lanes / pixel) ----------------
__global__ void __launch_bounds__(TB)
k1_proj(const float* __restrict__ x,
        const float* __restrict__ pm_w, const float* __restrict__ pm_b,
        const float* __restrict__ pa_w, const float* __restrict__ pa_b,
        const float* __restrict__ n1w) {
    int t = blockIdx.x * blockDim.x + threadIdx.x;
    int p = t >> 2, j = t & 3;
    int b = p >> 16;
    int hw = p & 0xFFFF;
    const float* xb = x + (size_t)b * 4 * HW;
    float x0 = xb[hw], x1 = xb[HW + hw], x2 = xb[2 * HW + hw], x3 = xb[3 * HW + hw];

    int c0 = 4 * j;
    float sc[4], f0[4];
    float ssp = 0.0f;
#pragma unroll
    for (int q = 0; q < 4; q++) {
        int c = c0 + q;
        float v = pm_w[c] * x0 + pm_b[c] + pa_b[c]
                + pa_w[c * 3 + 0] * x1 + pa_w[c * 3 + 1] * x2 + pa_w[c * 3 + 2] * x3;
        sc[q] = v;
        float g = geluf(v);
        f0[q] = g;
        ssp += g * g;
    }
    float ss = rsum4(ssp);
    float inv = 1.0f / (sqrtf(ss) * 0.25f + EPSF);

    g4_short[(size_t)p * 4 + j] = make_float4(sc[0], sc[1], sc[2], sc[3]);
    g4_feat0[(size_t)p * 4 + j] = make_float4(f0[0], f0[1], f0[2], f0[3]);
    gh_n1[(size_t)p * 4 + j] = f4toh4(make_float4(f0[0] * inv * n1w[c0],
                                                  f0[1] * inv * n1w[c0 + 1],
                                                  f0[2] * inv * n1w[c0 + 2],
                                                  f0[3] * inv * n1w[c0 + 3]));
}

// ---------------- deform core: half-gather, taps finished in phase 1 ----------
__device__ __forceinline__ float4 deform_core4(
    const uint2* __restrict__ sb, int y, int x, int lane, int j,
    const float* s_dww, const float* s_dwb,
    const float4* s_pw4, const float* s_pwb,
    float spacing, float mo, float4* tap_s, float* aux_s)
{
    const int c0 = 4 * j;

    // depthwise 3x3 (reflect) + bias, channel-split
    float4 h = make_float4(s_dwb[c0], s_dwb[c0 + 1], s_dwb[c0 + 2], s_dwb[c0 + 3]);
#pragma unroll
    for (int ky = 0; ky < 3; ky++) {
        int yy = reflecti(y + ky - 1);
#pragma unroll
        for (int kx = 0; kx < 3; kx++) {
            int xx = reflecti(x + kx - 1);
            float4 v = h4tof4(sb[(((yy << 8) + xx) << 2) + j]);
            const float* wb = s_dww + ky * 3 + kx;
            h.x = fmaf(v.x, wb[(c0 + 0) * 9], h.x);
            h.y = fmaf(v.y, wb[(c0 + 1) * 9], h.y);
            h.z = fmaf(v.z, wb[(c0 + 2) * 9], h.z);
            h.w = fmaf(v.w, wb[(c0 + 3) * 9], h.w);
        }
    }
    h.x = geluf(h.x); h.y = geluf(h.y); h.z = geluf(h.z); h.w = geluf(h.w);

    float4 hv[4];
    bcast16v(h, lane, hv);

    // phase 1: lane j owns k = j, j+4, ...
    for (int k = j; k < 25; k += 4) {
        const float4* wx4 = s_pw4 + (2 * k) * 5;
        const float4* wy4 = s_pw4 + (2 * k + 1) * 5;
        const float4* wl4 = s_pw4 + (50 + k) * 5;
        float px = s_pwb[2 * k], py = s_pwb[2 * k + 1], pl = s_pwb[50 + k];
#pragma unroll
        for (int q = 0; q < 4; q++) {
            px += dot44(hv[q], wx4[q]);
            py += dot44(hv[q], wy4[q]);
            pl += dot44(hv[q], wl4[q]);
        }
        float dx = spacing * (float)((k % 5) - 2) + tanh_p(px) * mo;
        float dy = spacing * (float)((k / 5) - 2) + tanh_p(py) * mo;
        float e = __expf(pl);
        TapPack tp = mk_tap_pack((float)x + dx, (float)y + dy);
        tap_s[k] = make_float4(__uint_as_float(tp.ua), __uint_as_float(tp.ub),
                               tp.wx, (1.0f - tp.wy) * e);
        aux_s[k] = tp.wy * e;
    }
    __syncwarp();

    // phase 2: pure gather (half loads)
    float4 acc = make_float4(0.f, 0.f, 0.f, 0.f);
    float den = 0.0f;
#pragma unroll 2
    for (int k = 0; k < 25; k++) {
        float4 tp = tap_s[k];
        float wye = aux_s[k];
        unsigned ua = __float_as_uint(tp.x), ub = __float_as_uint(tp.y);
        int i00 = ua & 0xffff, i01 = ua >> 16, i10 = ub & 0xffff, i11 = ub >> 16;
        float wx = tp.z, omye = tp.w;
        float omx = 1.0f - wx;
        acc = f4fma(omx * omye, h4tof4(sb[(i00 << 2) + j]), acc);
        acc = f4fma(wx * omye,  h4tof4(sb[(i01 << 2) + j]), acc);
        acc = f4fma(omx * wye,  h4tof4(sb[(i10 << 2) + j]), acc);
        acc = f4fma(wx * wye,   h4tof4(sb[(i11 << 2) + j]), acc);
        den += omye + wye;
    }
    return f4scale(1.0f / den, acc);
}

// ---------------- K2: fine deform  (n1 -> a1) ----------------
__global__ void __launch_bounds__(TB)
k2_fine(const float* __restrict__ dww, const float* __restrict__ dwb,
        const float* __restrict__ pww, const float* __restrict__ pwb) {
    __shared__ float s_dww[144], s_dwb[16], s_pwb[75];
    __shared__ float4 s_pw4[75 * 5];
    __shared__ float4 s_tap[TB / 4][25];
    __shared__ float s_aux[TB / 4][25];
    int tid = threadIdx.x;
    ldblk(s_dww, dww, 144, tid);
    ldblk(s_dwb, dwb, 16, tid);
    ldblk(s_pwb, pwb, 75, tid);
    ldpad((float*)s_pw4, pww, 75, tid);
    __syncthreads();

    int t = blockIdx.x * blockDim.x + tid;
    int p = t >> 2, j = t & 3;
    int lane = tid & 31;
    int g = tid >> 2;
    int b = p >> 16, y = (p >> 8) & 255, x = p & 255;
    const uint2* sb = gh_n1 + ((size_t)b << 18);
    float4 o = deform_core4(sb, y, x, lane, j, s_dww, s_dwb, s_pw4, s_pwb,
                            1.0f, 4.0f, &s_tap[g][0], &s_aux[g][0]);
    gh_a1[(size_t)p * 4 + j] = f4toh4(o);
}

// ---------------- K3: coarse deform + rmsnorm + gate + proj_out + sigma ----------------
__global__ void __launch_bounds__(TB)
k3_coarse_tail(const float* __restrict__ dww, const float* __restrict__ dwb,
               const float* __restrict__ pww, const float* __restrict__ pwb,
               const float* __restrict__ n2w,
               const float* __restrict__ gate_w, const float* __restrict__ gate_b,
               const float* __restrict__ pout_w, const float* __restrict__ pout_b,
               const float* __restrict__ sig_w, const float* __restrict__ sig_b) {
    __shared__ float s_dww[144], s_dwb[16], s_pwb[75], s_n2w[16], s_sigb[3];
    __shared__ float4 s_pw4[75 * 5];
    __shared__ float4 s_gT4[16 * 5], s_pT4[16 * 5];
    __shared__ float4 s_gb4[4], s_pb4[4], s_sig4[12];
    __shared__ float4 s_tap[TB / 4][25];
    __shared__ float s_aux[TB / 4][25];
    int tid = threadIdx.x;
    ldblk(s_dww, dww, 144, tid);
    ldblk(s_dwb, dwb, 16, tid);
    ldblk(s_pwb, pwb, 75, tid);
    ldpad((float*)s_pw4, pww, 75, tid);
    ldtpad((float*)s_gT4, gate_w, tid);
    ldtpad((float*)s_pT4, pout_w, tid);
    ldblk((float*)s_gb4, gate_b, 16, tid);
    ldblk((float*)s_pb4, pout_b, 16, tid);
    ldblk((float*)s_sig4, sig_w, 48, tid);
    ldblk(s_n2w, n2w, 16, tid);
    ldblk(s_sigb, sig_b, 3, tid);
    __syncthreads();

    int t = blockIdx.x * blockDim.x + tid;
    int p = t >> 2, j = t & 3;
    int lane = tid & 31;
    int g = tid >> 2;
    int b = p >> 16, y = (p >> 8) & 255, x = p & 255;
    const int c0 = 4 * j;
    const uint2* sb = gh_a1 + ((size_t)b << 18);

    float4 av = deform_core4(sb, y, x, lane, j, s_dww, s_dwb, s_pw4, s_pwb,
                             3.0f, 6.0f, &s_tap[g][0], &s_aux[g][0]);

    // rmsnorm(a2, norm2)
    float ssp = av.x * av.x + av.y * av.y + av.z * av.z + av.w * av.w;
    float ss = rsum4(ssp);
    float inv = 1.0f / (sqrtf(ss) * 0.25f + EPSF);
    float4 tv = make_float4(av.x * inv * s_n2w[c0], av.y * inv * s_n2w[c0 + 1],
                            av.z * inv * s_n2w[c0 + 2], av.w * inv * s_n2w[c0 + 3]);

    float4 tf[4];
    bcast16v(tv, lane, tf);

    float4 a3 = s_gb4[j];
#pragma unroll
    for (int r = 0; r < 4; r++) {
        a3 = f4fma(tf[r].x, s_gT4[(4 * r + 0) * 5 + j], a3);
        a3 = f4fma(tf[r].y, s_gT4[(4 * r + 1) * 5 + j], a3);
        a3 = f4fma(tf[r].z, s_gT4[(4 * r + 2) * 5 + j], a3);
        a3 = f4fma(tf[r].w, s_gT4[(4 * r + 3) * 5 + j], a3);
    }
    float4 f0v = g4_feat0[(size_t)p * 4 + j];
    float4 gv = make_float4(f0v.x * a3.x, f0v.y * a3.y, f0v.z * a3.z, f0v.w * a3.w);

    float4 gf[4];
    bcast16v(gv, lane, gf);

    float4 fv = f4add(s_pb4[j], g4_short[(size_t)p * 4 + j]);
#pragma unroll
    for (int r = 0; r < 4; r++) {
        fv = f4fma(gf[r].x, s_pT4[(4 * r + 0) * 5 + j], fv);
        fv = f4fma(gf[r].y, s_pT4[(4 * r + 1) * 5 + j], fv);
        fv = f4fma(gf[r].z, s_pT4[(4 * r + 2) * 5 + j], fv);
        fv = f4fma(gf[r].w, s_pT4[(4 * r + 3) * 5 + j], fv);
    }
    g4_feat[(size_t)p * 4 + j] = fv;
    gh_feat[(size_t)p * 4 + j] = f4toh4(fv);

    float sg[3];
#pragma unroll
    for (int r = 0; r < 3; r++) {
        float zp = dot44(fv, s_sig4[r * 4 + j]);
        float z = rsum4(zp) + s_sigb[r];
        float sp = fmaxf(z, 0.0f) + log1pf(expf(-fabsf(z)));
        sg[r] = fminf(sp, 6.0f) + EPSF;
    }
    if (j == 0) g_sig[p] = make_float4(sg[0], sg[1], sg[2], 0.0f);
}

// ---------------- K4: joint bilateral ----------------
__global__ void __launch_bounds__(TB)
k4_bilateral(const float* __restrict__ xin,
             const float* __restrict__ offw, const float* __restrict__ offb,
             float* __restrict__ out) {
    __shared__ float4 s_ow4[50 * 5];
    __shared__ float s_ob[50];
    __shared__ float4 s_tap[TB / 4][25];
    __shared__ float s_aux[TB / 4][25];   // spat
    int tid = threadIdx.x;
    ldpad((float*)s_ow4, offw, 50, tid);
    ldblk(s_ob, offb, 50, tid);
    __syncthreads();

    int t = blockIdx.x * blockDim.x + tid;
    int p = t >> 2, j = t & 3;
    int lane = tid & 31;
    int g = tid >> 2;
    int b = p >> 16, y = (p >> 8) & 255, x = p & 255;

    float4 fv = g4_feat[(size_t)p * 4 + j];
    float4 fvv[4];
    bcast16v(fv, lane, fvv);

    float4 s4 = g_sig[p];
    float axc = 0.5f / (s4.x * s4.x);
    float ayc = 0.5f / (s4.y * s4.y);
    float arc = 0.5f / (s4.z * s4.z);

    const float* plane = xin + (size_t)b * 4 * HW;
    const uint2* fb = gh_feat + ((size_t)b << 18);
    float4* tap_s = &s_tap[g][0];
    float* aux_s = &s_aux[g][0];

    // phase 1: lane j owns k = j, j+4, ... (compute only)
    for (int k = j; k < 25; k += 4) {
        const float4* wx4 = s_ow4 + (2 * k) * 5;
        const float4* wy4 = s_ow4 + (2 * k + 1) * 5;
        float px = s_ob[2 * k], py = s_ob[2 * k + 1];
#pragma unroll
        for (int q = 0; q < 4; q++) {
            px += dot44(fvv[q], wx4[q]);
            py += dot44(fvv[q], wy4[q]);
        }
        float dx = (float)((k % 5) - 2) + tanh_p(px) * 5.0f;
        float dy = (float)((k / 5) - 2) + tanh_p(py) * 5.0f;
        float spat = dx * dx * axc + dy * dy * ayc;
        TapPack tp = mk_tap_pack((float)x + dx, (float)y + dy);
        tap_s[k] = make_float4(__uint_as_float(tp.ua), __uint_as_float(tp.ub),
                               tp.wx, tp.wy);
        aux_s[k] = spat;
    }
    __syncwarp();

    // phase 2: feat gather (half) + corner-split patch; patch reduce deferred
    float num = 0.0f, den = 0.0f;
#pragma unroll 2
    for (int k = 0; k < 25; k++) {
        float4 tp = tap_s[k];
        float spat = aux_s[k];
        unsigned ua = __float_as_uint(tp.x), ub = __float_as_uint(tp.y);
        int i00 = ua & 0xffff, i01 = ua >> 16, i10 = ub & 0xffff, i11 = ub >> 16;
        float wx = tp.z, wy = tp.w;
        float omx = 1.0f - wx, omy = 1.0f - wy;
        float w00 = omx * omy, w01 = wx * omy, w10 = omx * wy, w11 = wx * wy;

        float4 s = f4scale(w00, h4tof4(fb[(i00 << 2) + j]));
        s = f4fma(w01, h4tof4(fb[(i01 << 2) + j]), s);
        s = f4fma(w10, h4tof4(fb[(i10 << 2) + j]), s);
        s = f4fma(w11, h4tof4(fb[(i11 << 2) + j]), s);
        float ddx = fv.x - s.x, ddy = fv.y - s.y, ddz = fv.z - s.z, ddw = fv.w - s.w;
        float fdp = ddx * ddx + ddy * ddy + ddz * ddz + ddw * ddw;

        // patch partial: lane j loads its corner only, reduce deferred to end
        int ci = (j & 2) ? ((j & 1) ? i11 : i10) : ((j & 1) ? i01 : i00);
        float cw = (j & 2) ? ((j & 1) ? w11 : w10) : ((j & 1) ? w01 : w00);
        float pp = cw * plane[ci];

        float fd = rsum4(fdp);
        float w = __expf(-spat - fd * arc);
        num = fmaf(pp, w, num);      // lane-partial numerator
        den += w;                    // group-uniform
    }
    num = rsum4(num);
    if (j == 0) out[p] = num / (den + 1e-8f);
}

// ---------------- launch ----------------
extern "C" void kernel_launch(void* const* d_in, const int* in_sizes, int n_in,
                              void* d_out, int out_size) {
    const float* x = (const float*)d_in[0];
    const int NB4 = (NPIX * 4) / TB;   // 4 lanes per pixel

    k1_proj<<<NB4, TB>>>(x, (const float*)d_in[1], (const float*)d_in[2],
                         (const float*)d_in[3], (const float*)d_in[4],
                         (const float*)d_in[5]);
    k2_fine<<<NB4, TB>>>((const float*)d_in[6], (const float*)d_in[7],
                         (const float*)d_in[8], (const float*)d_in[9]);
    k3_coarse_tail<<<NB4, TB>>>((const float*)d_in[10], (const float*)d_in[11],
                                (const float*)d_in[12], (const float*)d_in[13],
                                (const float*)d_in[14],
                                (const float*)d_in[15], (const float*)d_in[16],
                                (const float*)d_in[17], (const float*)d_in[18],
                                (const float*)d_in[19], (const float*)d_in[20]);
    k4_bilateral<<<NB4, TB>>>(x, (const float*)d_in[21], (const float*)d_in[22],
                              (float*)d_out);
}

// round 9
// speedup vs baseline: 1.2530x; 1.0059x over previous
#include <cuda_runtime.h>
#include <cuda_fp16.h>
#include <math.h>

#define NPIX  131072            // B*H*W = 2*256*256
#define HW    65536
#define EPSF  1e-6f
#define TB    256

// ---------------- scratch (static __device__, no allocation) ----------------
__device__ float4 g4_short[NPIX * 4];
__device__ float4 g4_feat0[NPIX * 4];
__device__ float4 g4_feat[NPIX * 4];       // fp32 feat (center reads in k4)
__device__ uint2  gh_n1[NPIX * 4];         // half x4 per lane chunk
__device__ uint2  gh_a1[NPIX * 4];
__device__ uint2  gh_feat[NPIX * 4];
__device__ float4 g_sig[NPIX];             // (sx, sy, sr, -)

// ---------------- helpers ----------------
__device__ __forceinline__ float4 f4fma(float a, float4 b, float4 c) {
    return make_float4(fmaf(a, b.x, c.x), fmaf(a, b.y, c.y),
                       fmaf(a, b.z, c.z), fmaf(a, b.w, c.w));
}
__device__ __forceinline__ float4 f4scale(float a, float4 b) {
    return make_float4(a * b.x, a * b.y, a * b.z, a * b.w);
}
__device__ __forceinline__ float4 f4add(float4 a, float4 b) {
    return make_float4(a.x + b.x, a.y + b.y, a.z + b.z, a.w + b.w);
}
__device__ __forceinline__ float dot44(float4 a, float4 b) {
    return fmaf(a.x, b.x, fmaf(a.y, b.y, fmaf(a.z, b.z, a.w * b.w)));
}
__device__ __forceinline__ float rsum4(float v) {
    v += __shfl_xor_sync(0xffffffffu, v, 1);
    v += __shfl_xor_sync(0xffffffffu, v, 2);
    return v;
}
__device__ __forceinline__ void bcast16v(float4 v, int lane, float4 out[4]) {
    int base = lane & ~3;
#pragma unroll
    for (int q = 0; q < 4; q++) {
        out[q] = make_float4(__shfl_sync(0xffffffffu, v.x, base + q),
                             __shfl_sync(0xffffffffu, v.y, base + q),
                             __shfl_sync(0xffffffffu, v.z, base + q),
                             __shfl_sync(0xffffffffu, v.w, base + q));
    }
}
__device__ __forceinline__ float4 h4tof4(uint2 u) {
    __half2 h0 = *reinterpret_cast<__half2*>(&u.x);
    __half2 h1 = *reinterpret_cast<__half2*>(&u.y);
    float2 a = __half22float2(h0), b = __half22float2(h1);
    return make_float4(a.x, a.y, b.x, b.y);
}
__device__ __forceinline__ uint2 f4toh4(float4 v) {
    __half2 h0 = __floats2half2_rn(v.x, v.y);
    __half2 h1 = __floats2half2_rn(v.z, v.w);
    uint2 u;
    u.x = *reinterpret_cast<unsigned*>(&h0);
    u.y = *reinterpret_cast<unsigned*>(&h1);
    return u;
}
__device__ __forceinline__ float geluf(float v) {
    return 0.5f * v * (1.0f + erff(v * 0.7071067811865476f));
}
__device__ __forceinline__ float tanh_p(float x) {
    float ax = fabsf(x);
    float e = __expf(2.0f * ax);
    float t = 1.0f - 2.0f / (e + 1.0f);
    return copysignf(t, x);
}
// valid for |c| < 510 (always true here: |offset| <= 12, x in [0,255])
__device__ __forceinline__ float reflectf(float c) {
    float a = fabsf(c);
    return a > 255.0f ? 510.0f - a : a;
}
__device__ __forceinline__ int reflecti(int i) {
    i = abs(i);
    return i > 255 ? 510 - i : i;
}
// bilinear weights + packed index (i00 | sx<<16 | sy<<17)
struct TapW { float4 w; unsigned u; };
__device__ __forceinline__ TapW mk_tap_w(float ix, float iy, float scale) {
    ix = reflectf(ix);
    iy = reflectf(iy);
    float fx = floorf(ix), fy = floorf(iy);
    float wx = ix - fx, wy = iy - fy;
    int x0 = (int)fx, y0 = (int)fy;
    TapW t;
    t.u = (unsigned)((y0 << 8) + x0);
    if (x0 < 255) t.u |= 1u << 16;
    if (y0 < 255) t.u |= 1u << 17;
    float omx = 1.0f - wx, omy = 1.0f - wy;
    float omye = omy * scale, wye = wy * scale;
    t.w = make_float4(omx * omye, wx * omye, omx * wye, wx * wye);
    return t;
}
// unpack: i00, i01, i10, i11
__device__ __forceinline__ void unpack_tap(unsigned u, int& i00, int& i01, int& i10, int& i11) {
    i00 = u & 0xffff;
    int sx = (u >> 16) & 1;
    i01 = i00 + sx;
    i10 = i00 + ((u >> 9) & 0x100);
    i11 = i10 + sx;
}

// ---------------- smem loaders (TB threads) ----------------
__device__ __forceinline__ void ldblk(float* dst, const float* src, int n, int tid) {
    for (int i = tid; i < n; i += TB) dst[i] = src[i];
}
__device__ __forceinline__ void ldpad(float* dst, const float* src, int rows, int tid) {
    for (int i = tid; i < rows * 16; i += TB) {
        int r = i >> 4, c = i & 15;
        dst[r * 20 + c] = src[i];
    }
}
__device__ __forceinline__ void ldtpad(float* dst, const float* src, int tid) {
    for (int i = tid; i < 256; i += TB) {
        int o = i >> 4, c = i & 15;
        dst[c * 20 + o] = src[i];
    }
}

// ---------------- K1: proj + gelu + rmsnorm (4 lanes / pixel) ----------------
__global__ void __launch_bounds__(TB)
k1_proj(const float* __restrict__ x,
        const float* __restrict__ pm_w, const float* __restrict__ pm_b,
        const float* __restrict__ pa_w, const float* __restrict__ pa_b,
        const float* __restrict__ n1w) {
    int t = blockIdx.x * blockDim.x + threadIdx.x;
    int p = t >> 2, j = t & 3;
    int b = p >> 16;
    int hw = p & 0xFFFF;
    const float* xb = x + (size_t)b * 4 * HW;
    float x0 = xb[hw], x1 = xb[HW + hw], x2 = xb[2 * HW + hw], x3 = xb[3 * HW + hw];

    int c0 = 4 * j;
    float sc[4], f0[4];
    float ssp = 0.0f;
#pragma unroll
    for (int q = 0; q < 4; q++) {
        int c = c0 + q;
        float v = pm_w[c] * x0 + pm_b[c] + pa_b[c]
                + pa_w[c * 3 + 0] * x1 + pa_w[c * 3 + 1] * x2 + pa_w[c * 3 + 2] * x3;
        sc[q] = v;
        float g = geluf(v);
        f0[q] = g;
        ssp += g * g;
    }
    float ss = rsum4(ssp);
    float inv = 1.0f / (sqrtf(ss) * 0.25f + EPSF);

    g4_short[(size_t)p * 4 + j] = make_float4(sc[0], sc[1], sc[2], sc[3]);
    g4_feat0[(size_t)p * 4 + j] = make_float4(f0[0], f0[1], f0[2], f0[3]);
    gh_n1[(size_t)p * 4 + j] = f4toh4(make_float4(f0[0] * inv * n1w[c0],
                                                  f0[1] * inv * n1w[c0 + 1],
                                                  f0[2] * inv * n1w[c0 + 2],
                                                  f0[3] * inv * n1w[c0 + 3]));
}

// ---------------- deform core: weights+den finished in phase 1 ----------------
__device__ __forceinline__ float4 deform_core4(
    const uint2* __restrict__ sb, int y, int x, int lane, int j,
    const float* s_dww, const float* s_dwb,
    const float4* s_pw4, const float* s_pwb,
    float spacing, float mo, float4* tap_s, unsigned* idx_s)
{
    const int c0 = 4 * j;

    // depthwise 3x3 (reflect) + bias, channel-split
    float4 h = make_float4(s_dwb[c0], s_dwb[c0 + 1], s_dwb[c0 + 2], s_dwb[c0 + 3]);
#pragma unroll
    for (int ky = 0; ky < 3; ky++) {
        int yy = reflecti(y + ky - 1);
#pragma unroll
        for (int kx = 0; kx < 3; kx++) {
            int xx = reflecti(x + kx - 1);
            float4 v = h4tof4(sb[(((yy << 8) + xx) << 2) + j]);
            const float* wb = s_dww + ky * 3 + kx;
            h.x = fmaf(v.x, wb[(c0 + 0) * 9], h.x);
            h.y = fmaf(v.y, wb[(c0 + 1) * 9], h.y);
            h.z = fmaf(v.z, wb[(c0 + 2) * 9], h.z);
            h.w = fmaf(v.w, wb[(c0 + 3) * 9], h.w);
        }
    }
    h.x = geluf(h.x); h.y = geluf(h.y); h.z = geluf(h.z); h.w = geluf(h.w);

    float4 hv[4];
    bcast16v(h, lane, hv);

    // phase 1: lane j owns k = j, j+4, ...  (weights pre-scaled by e; den here)
    float denp = 0.0f;
    for (int k = j; k < 25; k += 4) {
        const float4* wx4 = s_pw4 + (2 * k) * 5;
        const float4* wy4 = s_pw4 + (2 * k + 1) * 5;
        const float4* wl4 = s_pw4 + (50 + k) * 5;
        float px = s_pwb[2 * k], py = s_pwb[2 * k + 1], pl = s_pwb[50 + k];
#pragma unroll
        for (int q = 0; q < 4; q++) {
            px += dot44(hv[q], wx4[q]);
            py += dot44(hv[q], wy4[q]);
            pl += dot44(hv[q], wl4[q]);
        }
        float dx = spacing * (float)((k % 5) - 2) + tanh_p(px) * mo;
        float dy = spacing * (float)((k / 5) - 2) + tanh_p(py) * mo;
        float e = __expf(pl);
        denp += e;
        TapW tp = mk_tap_w((float)x + dx, (float)y + dy, e);
        tap_s[k] = tp.w;
        idx_s[k] = tp.u;
    }
    __syncwarp();
    float den = rsum4(denp);

    // phase 2: pure blend (half loads, pre-scaled weights)
    float4 acc = make_float4(0.f, 0.f, 0.f, 0.f);
#pragma unroll 2
    for (int k = 0; k < 25; k++) {
        float4 w = tap_s[k];
        int i00, i01, i10, i11;
        unpack_tap(idx_s[k], i00, i01, i10, i11);
        acc = f4fma(w.x, h4tof4(sb[(i00 << 2) + j]), acc);
        acc = f4fma(w.y, h4tof4(sb[(i01 << 2) + j]), acc);
        acc = f4fma(w.z, h4tof4(sb[(i10 << 2) + j]), acc);
        acc = f4fma(w.w, h4tof4(sb[(i11 << 2) + j]), acc);
    }
    return f4scale(1.0f / den, acc);
}

// ---------------- K2: fine deform  (n1 -> a1) ----------------
__global__ void __launch_bounds__(TB)
k2_fine(const float* __restrict__ dww, const float* __restrict__ dwb,
        const float* __restrict__ pww, const float* __restrict__ pwb) {
    __shared__ float s_dww[144], s_dwb[16], s_pwb[75];
    __shared__ float4 s_pw4[75 * 5];
    __shared__ float4 s_tap[TB / 4][25];
    __shared__ unsigned s_idx[TB / 4][25];
    int tid = threadIdx.x;
    ldblk(s_dww, dww, 144, tid);
    ldblk(s_dwb, dwb, 16, tid);
    ldblk(s_pwb, pwb, 75, tid);
    ldpad((float*)s_pw4, pww, 75, tid);
    __syncthreads();

    int t = blockIdx.x * blockDim.x + tid;
    int p = t >> 2, j = t & 3;
    int lane = tid & 31;
    int g = tid >> 2;
    int b = p >> 16, y = (p >> 8) & 255, x = p & 255;
    const uint2* sb = gh_n1 + ((size_t)b << 18);
    float4 o = deform_core4(sb, y, x, lane, j, s_dww, s_dwb, s_pw4, s_pwb,
                            1.0f, 4.0f, &s_tap[g][0], &s_idx[g][0]);
    gh_a1[(size_t)p * 4 + j] = f4toh4(o);
}

// ---------------- K3: coarse deform + rmsnorm + gate + proj_out + sigma ----------------
__global__ void __launch_bounds__(TB)
k3_coarse_tail(const float* __restrict__ dww, const float* __restrict__ dwb,
               const float* __restrict__ pww, const float* __restrict__ pwb,
               const float* __restrict__ n2w,
               const float* __restrict__ gate_w, const float* __restrict__ gate_b,
               const float* __restrict__ pout_w, const float* __restrict__ pout_b,
               const float* __restrict__ sig_w, const float* __restrict__ sig_b) {
    __shared__ float s_dww[144], s_dwb[16], s_pwb[75], s_n2w[16], s_sigb[3];
    __shared__ float4 s_pw4[75 * 5];
    __shared__ float4 s_gT4[16 * 5], s_pT4[16 * 5];
    __shared__ float4 s_gb4[4], s_pb4[4], s_sig4[12];
    __shared__ float4 s_tap[TB / 4][25];
    __shared__ unsigned s_idx[TB / 4][25];
    int tid = threadIdx.x;
    ldblk(s_dww, dww, 144, tid);
    ldblk(s_dwb, dwb, 16, tid);
    ldblk(s_pwb, pwb, 75, tid);
    ldpad((float*)s_pw4, pww, 75, tid);
    ldtpad((float*)s_gT4, gate_w, tid);
    ldtpad((float*)s_pT4, pout_w, tid);
    ldblk((float*)s_gb4, gate_b, 16, tid);
    ldblk((float*)s_pb4, pout_b, 16, tid);
    ldblk((float*)s_sig4, sig_w, 48, tid);
    ldblk(s_n2w, n2w, 16, tid);
    ldblk(s_sigb, sig_b, 3, tid);
    __syncthreads();

    int t = blockIdx.x * blockDim.x + tid;
    int p = t >> 2, j = t & 3;
    int lane = tid & 31;
    int g = tid >> 2;
    int b = p >> 16, y = (p >> 8) & 255, x = p & 255;
    const int c0 = 4 * j;
    const uint2* sb = gh_a1 + ((size_t)b << 18);

    float4 av = deform_core4(sb, y, x, lane, j, s_dww, s_dwb, s_pw4, s_pwb,
                             3.0f, 6.0f, &s_tap[g][0], &s_idx[g][0]);

    // rmsnorm(a2, norm2)
    float ssp = av.x * av.x + av.y * av.y + av.z * av.z + av.w * av.w;
    float ss = rsum4(ssp);
    float inv = 1.0f / (sqrtf(ss) * 0.25f + EPSF);
    float4 tv = make_float4(av.x * inv * s_n2w[c0], av.y * inv * s_n2w[c0 + 1],
                            av.z * inv * s_n2w[c0 + 2], av.w * inv * s_n2w[c0 + 3]);

    float4 tf[4];
    bcast16v(tv, lane, tf);

    float4 a3 = s_gb4[j];
#pragma unroll
    for (int r = 0; r < 4; r++) {
        a3 = f4fma(tf[r].x, s_gT4[(4 * r + 0) * 5 + j], a3);
        a3 = f4fma(tf[r].y, s_gT4[(4 * r + 1) * 5 + j], a3);
        a3 = f4fma(tf[r].z, s_gT4[(4 * r + 2) * 5 + j], a3);
        a3 = f4fma(tf[r].w, s_gT4[(4 * r + 3) * 5 + j], a3);
    }
    float4 f0v = g4_feat0[(size_t)p * 4 + j];
    float4 gv = make_float4(f0v.x * a3.x, f0v.y * a3.y, f0v.z * a3.z, f0v.w * a3.w);

    float4 gf[4];
    bcast16v(gv, lane, gf);

    float4 fv = f4add(s_pb4[j], g4_short[(size_t)p * 4 + j]);
#pragma unroll
    for (int r = 0; r < 4; r++) {
        fv = f4fma(gf[r].x, s_pT4[(4 * r + 0) * 5 + j], fv);
        fv = f4fma(gf[r].y, s_pT4[(4 * r + 1) * 5 + j], fv);
        fv = f4fma(gf[r].z, s_pT4[(4 * r + 2) * 5 + j], fv);
        fv = f4fma(gf[r].w, s_pT4[(4 * r + 3) * 5 + j], fv);
    }
    g4_feat[(size_t)p * 4 + j] = fv;
    gh_feat[(size_t)p * 4 + j] = f4toh4(fv);

    float sg[3];
#pragma unroll
    for (int r = 0; r < 3; r++) {
        float zp = dot44(fv, s_sig4[r * 4 + j]);
        float z = rsum4(zp) + s_sigb[r];
        float sp = fmaxf(z, 0.0f) + log1pf(expf(-fabsf(z)));
        sg[r] = fminf(sp, 6.0f) + EPSF;
    }
    if (j == 0) g_sig[p] = make_float4(sg[0], sg[1], sg[2], 0.0f);
}

// ---------------- K4: joint bilateral ----------------
__global__ void __launch_bounds__(TB)
k4_bilateral(const float* __restrict__ xin,
             const float* __restrict__ offw, const float* __restrict__ offb,
             float* __restrict__ out) {
    __shared__ float4 s_ow4[50 * 5];
    __shared__ float s_ob[50];
    __shared__ float4 s_tap[TB / 4][25];
    __shared__ float2 s_aux[TB / 4][25];   // (packed idx bits, spat)
    int tid = threadIdx.x;
    ldpad((float*)s_ow4, offw, 50, tid);
    ldblk(s_ob, offb, 50, tid);
    __syncthreads();

    int t = blockIdx.x * blockDim.x + tid;
    int p = t >> 2, j = t & 3;
    int lane = tid & 31;
    int g = tid >> 2;
    int b = p >> 16, y = (p >> 8) & 255, x = p & 255;

    float4 fv = g4_feat[(size_t)p * 4 + j];
    float4 fvv[4];
    bcast16v(fv, lane, fvv);

    float4 s4 = g_sig[p];
    float axc = 0.5f / (s4.x * s4.x);
    float ayc = 0.5f / (s4.y * s4.y);
    float arc = 0.5f / (s4.z * s4.z);

    const float* plane = xin + (size_t)b * 4 * HW;
    const uint2* fb = gh_feat + ((size_t)b << 18);
    float4* tap_s = &s_tap[g][0];
    float2* aux_s = &s_aux[g][0];

    // phase 1: lane j owns k = j, j+4, ... (compute only)
    for (int k = j; k < 25; k += 4) {
        const float4* wx4 = s_ow4 + (2 * k) * 5;
        const float4* wy4 = s_ow4 + (2 * k + 1) * 5;
        float px = s_ob[2 * k], py = s_ob[2 * k + 1];
#pragma unroll
        for (int q = 0; q < 4; q++) {
            px += dot44(fvv[q], wx4[q]);
            py += dot44(fvv[q], wy4[q]);
        }
        float dx = (float)((k % 5) - 2) + tanh_p(px) * 5.0f;
        float dy = (float)((k / 5) - 2) + tanh_p(py) * 5.0f;
        float spat = dx * dx * axc + dy * dy * ayc;
        TapW tp = mk_tap_w((float)x + dx, (float)y + dy, 1.0f);
        tap_s[k] = tp.w;
        aux_s[k] = make_float2(__uint_as_float(tp.u), spat);
    }
    __syncwarp();

    // phase 2: feat gather (half) + corner-split patch; patch reduce deferred
    float num = 0.0f, den = 0.0f;
#pragma unroll 2
    for (int k = 0; k < 25; k++) {
        float4 w = tap_s[k];
        float2 a2 = aux_s[k];
        int i00, i01, i10, i11;
        unpack_tap(__float_as_uint(a2.x), i00, i01, i10, i11);

        float4 s = f4scale(w.x, h4tof4(fb[(i00 << 2) + j]));
        s = f4fma(w.y, h4tof4(fb[(i01 << 2) + j]), s);
        s = f4fma(w.z, h4tof4(fb[(i10 << 2) + j]), s);
        s = f4fma(w.w, h4tof4(fb[(i11 << 2) + j]), s);
        float ddx = fv.x - s.x, ddy = fv.y - s.y, ddz = fv.z - s.z, ddw = fv.w - s.w;
        float fdp = ddx * ddx + ddy * ddy + ddz * ddz + ddw * ddw;

        // patch partial: lane j loads its corner only, reduce deferred to end
        int ci = (j & 2) ? ((j & 1) ? i11 : i10) : ((j & 1) ? i01 : i00);
        float cw = (j & 2) ? ((j & 1) ? w.w : w.z) : ((j & 1) ? w.y : w.x);
        float pp = cw * plane[ci];

        float fd = rsum4(fdp);
        float wgt = __expf(-a2.y - fd * arc);
        num = fmaf(pp, wgt, num);    // lane-partial numerator
        den += wgt;                  // group-uniform
    }
    num = rsum4(num);
    if (j == 0) out[p] = num / (den + 1e-8f);
}

// ---------------- launch ----------------
extern "C" void kernel_launch(void* const* d_in, const int* in_sizes, int n_in,
                              void* d_out, int out_size) {
    const float* x = (const float*)d_in[0];
    const int NB4 = (NPIX * 4) / TB;   // 4 lanes per pixel

    k1_proj<<<NB4, TB>>>(x, (const float*)d_in[1], (const float*)d_in[2],
                         (const float*)d_in[3], (const float*)d_in[4],
                         (const float*)d_in[5]);
    k2_fine<<<NB4, TB>>>((const float*)d_in[6], (const float*)d_in[7],
                         (const float*)d_in[8], (const float*)d_in[9]);
    k3_coarse_tail<<<NB4, TB>>>((const float*)d_in[10], (const float*)d_in[11],
                                (const float*)d_in[12], (const float*)d_in[13],
                                (const float*)d_in[14],
                                (const float*)d_in[15], (const float*)d_in[16],
                                (const float*)d_in[17], (const float*)d_in[18],
                                (const float*)d_in[19], (const float*)d_in[20]);
    k4_bilateral<<<NB4, TB>>>(x, (const float*)d_in[21], (const float*)d_in[22],
                              (float*)d_out);
}

// round 10
// speedup vs baseline: 1.3246x; 1.0571x over previous
#include <cuda_runtime.h>
#include <cuda_fp16.h>
#include <math.h>

#define NPIX  131072            // B*H*W = 2*256*256
#define HW    65536
#define EPSF  1e-6f
#define TB    256

// ---------------- scratch (static __device__, no allocation) ----------------
__device__ float4 g4_short[NPIX * 4];
__device__ float4 g4_feat0[NPIX * 4];
__device__ float4 g4_feat[NPIX * 4];       // fp32 feat (center reads in k4)
__device__ uint2  gh_n1[NPIX * 4];         // half x4 per lane chunk
__device__ uint2  gh_a1[NPIX * 4];
__device__ uint2  gh_feat[NPIX * 4];
__device__ float4 g_sig[NPIX];             // (sx, sy, sr, -)

// ---------------- helpers ----------------
__device__ __forceinline__ float4 f4fma(float a, float4 b, float4 c) {
    return make_float4(fmaf(a, b.x, c.x), fmaf(a, b.y, c.y),
                       fmaf(a, b.z, c.z), fmaf(a, b.w, c.w));
}
__device__ __forceinline__ float4 f4scale(float a, float4 b) {
    return make_float4(a * b.x, a * b.y, a * b.z, a * b.w);
}
__device__ __forceinline__ float4 f4add(float4 a, float4 b) {
    return make_float4(a.x + b.x, a.y + b.y, a.z + b.z, a.w + b.w);
}
__device__ __forceinline__ float dot44(float4 a, float4 b) {
    return fmaf(a.x, b.x, fmaf(a.y, b.y, fmaf(a.z, b.z, a.w * b.w)));
}
__device__ __forceinline__ float rsum4(float v) {
    v += __shfl_xor_sync(0xffffffffu, v, 1);
    v += __shfl_xor_sync(0xffffffffu, v, 2);
    return v;
}
__device__ __forceinline__ void bcast16v(float4 v, int lane, float4 out[4]) {
    int base = lane & ~3;
#pragma unroll
    for (int q = 0; q < 4; q++) {
        out[q] = make_float4(__shfl_sync(0xffffffffu, v.x, base + q),
                             __shfl_sync(0xffffffffu, v.y, base + q),
                             __shfl_sync(0xffffffffu, v.z, base + q),
                             __shfl_sync(0xffffffffu, v.w, base + q));
    }
}
__device__ __forceinline__ float4 h4tof4(uint2 u) {
    __half2 h0 = *reinterpret_cast<__half2*>(&u.x);
    __half2 h1 = *reinterpret_cast<__half2*>(&u.y);
    float2 a = __half22float2(h0), b = __half22float2(h1);
    return make_float4(a.x, a.y, b.x, b.y);
}
__device__ __forceinline__ uint2 f4toh4(float4 v) {
    __half2 h0 = __floats2half2_rn(v.x, v.y);
    __half2 h1 = __floats2half2_rn(v.z, v.w);
    uint2 u;
    u.x = *reinterpret_cast<unsigned*>(&h0);
    u.y = *reinterpret_cast<unsigned*>(&h1);
    return u;
}
__device__ __forceinline__ float geluf(float v) {
    return 0.5f * v * (1.0f + erff(v * 0.7071067811865476f));
}
__device__ __forceinline__ float tanh_p(float x) {
    float ax = fabsf(x);
    float e = __expf(2.0f * ax);
    float t = 1.0f - 2.0f / (e + 1.0f);
    return copysignf(t, x);
}
// valid for |c| < 510 (always true here: |offset| <= 12, x in [0,255])
__device__ __forceinline__ float reflectf(float c) {
    float a = fabsf(c);
    return a > 255.0f ? 510.0f - a : a;
}
__device__ __forceinline__ int reflecti(int i) {
    i = abs(i);
    return i > 255 ? 510 - i : i;
}
// ---- deform tap: weights pre-scaled, single packed idx (i00 | sx<<16 | sy<<17)
struct TapW { float4 w; unsigned u; };
__device__ __forceinline__ TapW mk_tap_w(float ix, float iy, float scale) {
    ix = reflectf(ix);
    iy = reflectf(iy);
    float fx = floorf(ix), fy = floorf(iy);
    float wx = ix - fx, wy = iy - fy;
    int x0 = (int)fx, y0 = (int)fy;
    TapW t;
    t.u = (unsigned)((y0 << 8) + x0);
    if (x0 < 255) t.u |= 1u << 16;
    if (y0 < 255) t.u |= 1u << 17;
    float omx = 1.0f - wx, omy = 1.0f - wy;
    float omye = omy * scale, wye = wy * scale;
    t.w = make_float4(omx * omye, wx * omye, omx * wye, wx * wye);
    return t;
}
__device__ __forceinline__ void unpack_tap(unsigned u, int& i00, int& i01, int& i10, int& i11) {
    i00 = u & 0xffff;
    int sx = (u >> 16) & 1;
    i01 = i00 + sx;
    i10 = i00 + ((u >> 9) & 0x100);
    i11 = i10 + sx;
}
// ---- k4 tap: explicit packed pairs (R8 layout)
struct TapPack { unsigned ua, ub; float wx, wy; };
__device__ __forceinline__ TapPack mk_tap_pack(float ix, float iy) {
    ix = reflectf(ix);
    iy = reflectf(iy);
    float fx = floorf(ix), fy = floorf(iy);
    TapPack t;
    t.wx = ix - fx;  t.wy = iy - fy;
    int x0 = (int)fx, y0 = (int)fy;
    int x1 = min(x0 + 1, 255), y1 = min(y0 + 1, 255);
    int r0 = y0 << 8, r1 = y1 << 8;
    t.ua = (unsigned)(r0 + x0) | ((unsigned)(r0 + x1) << 16);
    t.ub = (unsigned)(r1 + x0) | ((unsigned)(r1 + x1) << 16);
    return t;
}

// 8x8 tile mapping: block -> (batch, tile-y, tile-x); group g in block -> pixel
__device__ __forceinline__ int tile_pixel(int bi, int g) {
    int b = bi >> 10;                 // 1024 tiles per batch image
    int ty = (bi >> 5) & 31;
    int tx = bi & 31;
    int y = (ty << 3) + (g >> 3);
    int x = (tx << 3) + (g & 7);
    return (b << 16) | (y << 8) | x;
}

// ---------------- smem loaders (TB threads) ----------------
__device__ __forceinline__ void ldblk(float* dst, const float* src, int n, int tid) {
    for (int i = tid; i < n; i += TB) dst[i] = src[i];
}
__device__ __forceinline__ void ldpad(float* dst, const float* src, int rows, int tid) {
    for (int i = tid; i < rows * 16; i += TB) {
        int r = i >> 4, c = i & 15;
        dst[r * 20 + c] = src[i];
    }
}
__device__ __forceinline__ void ldtpad(float* dst, const float* src, int tid) {
    for (int i = tid; i < 256; i += TB) {
        int o = i >> 4, c = i & 15;
        dst[c * 20 + o] = src[i];
    }
}

// ---------------- K1: proj + gelu + rmsnorm (4 lanes / pixel) ----------------
__global__ void __launch_bounds__(TB)
k1_proj(const float* __restrict__ x,
        const float* __restrict__ pm_w, const float* __restrict__ pm_b,
        const float* __restrict__ pa_w, const float* __restrict__ pa_b,
        const float* __restrict__ n1w) {
    int tid = threadIdx.x;
    int p = tile_pixel(blockIdx.x, tid >> 2);
    int j = tid & 3;
    int b = p >> 16;
    int hw = p & 0xFFFF;
    const float* xb = x + (size_t)b * 4 * HW;
    float x0 = xb[hw], x1 = xb[HW + hw], x2 = xb[2 * HW + hw], x3 = xb[3 * HW + hw];

    int c0 = 4 * j;
    float sc[4], f0[4];
    float ssp = 0.0f;
#pragma unroll
    for (int q = 0; q < 4; q++) {
        int c = c0 + q;
        float v = pm_w[c] * x0 + pm_b[c] + pa_b[c]
                + pa_w[c * 3 + 0] * x1 + pa_w[c * 3 + 1] * x2 + pa_w[c * 3 + 2] * x3;
        sc[q] = v;
        float g = geluf(v);
        f0[q] = g;
        ssp += g * g;
    }
    float ss = rsum4(ssp);
    float inv = 1.0f / (sqrtf(ss) * 0.25f + EPSF);

    g4_short[(size_t)p * 4 + j] = make_float4(sc[0], sc[1], sc[2], sc[3]);
    g4_feat0[(size_t)p * 4 + j] = make_float4(f0[0], f0[1], f0[2], f0[3]);
    gh_n1[(size_t)p * 4 + j] = f4toh4(make_float4(f0[0] * inv * n1w[c0],
                                                  f0[1] * inv * n1w[c0 + 1],
                                                  f0[2] * inv * n1w[c0 + 2],
                                                  f0[3] * inv * n1w[c0 + 3]));
}

// ---------------- deform core: weights+den finished in phase 1 ----------------
__device__ __forceinline__ float4 deform_core4(
    const uint2* __restrict__ sb, int y, int x, int lane, int j,
    const float* s_dww, const float* s_dwb,
    const float4* s_pw4, const float* s_pwb,
    float spacing, float mo, float4* tap_s, unsigned* idx_s)
{
    const int c0 = 4 * j;

    // depthwise 3x3 (reflect) + bias, channel-split
    float4 h = make_float4(s_dwb[c0], s_dwb[c0 + 1], s_dwb[c0 + 2], s_dwb[c0 + 3]);
#pragma unroll
    for (int ky = 0; ky < 3; ky++) {
        int yy = reflecti(y + ky - 1);
#pragma unroll
        for (int kx = 0; kx < 3; kx++) {
            int xx = reflecti(x + kx - 1);
            float4 v = h4tof4(sb[(((yy << 8) + xx) << 2) + j]);
            const float* wb = s_dww + ky * 3 + kx;
            h.x = fmaf(v.x, wb[(c0 + 0) * 9], h.x);
            h.y = fmaf(v.y, wb[(c0 + 1) * 9], h.y);
            h.z = fmaf(v.z, wb[(c0 + 2) * 9], h.z);
            h.w = fmaf(v.w, wb[(c0 + 3) * 9], h.w);
        }
    }
    h.x = geluf(h.x); h.y = geluf(h.y); h.z = geluf(h.z); h.w = geluf(h.w);

    float4 hv[4];
    bcast16v(h, lane, hv);

    // phase 1: lane j owns k = j, j+4, ...  (weights pre-scaled by e; den here)
    float denp = 0.0f;
    for (int k = j; k < 25; k += 4) {
        const float4* wx4 = s_pw4 + (2 * k) * 5;
        const float4* wy4 = s_pw4 + (2 * k + 1) * 5;
        const float4* wl4 = s_pw4 + (50 + k) * 5;
        float px = s_pwb[2 * k], py = s_pwb[2 * k + 1], pl = s_pwb[50 + k];
#pragma unroll
        for (int q = 0; q < 4; q++) {
            px += dot44(hv[q], wx4[q]);
            py += dot44(hv[q], wy4[q]);
            pl += dot44(hv[q], wl4[q]);
        }
        float dx = spacing * (float)((k % 5) - 2) + tanh_p(px) * mo;
        float dy = spacing * (float)((k / 5) - 2) + tanh_p(py) * mo;
        float e = __expf(pl);
        denp += e;
        TapW tp = mk_tap_w((float)x + dx, (float)y + dy, e);
        tap_s[k] = tp.w;
        idx_s[k] = tp.u;
    }
    __syncwarp();
    float den = rsum4(denp);

    // phase 2: pure blend (half loads, pre-scaled weights)
    float4 acc = make_float4(0.f, 0.f, 0.f, 0.f);
#pragma unroll 2
    for (int k = 0; k < 25; k++) {
        float4 w = tap_s[k];
        int i00, i01, i10, i11;
        unpack_tap(idx_s[k], i00, i01, i10, i11);
        acc = f4fma(w.x, h4tof4(sb[(i00 << 2) + j]), acc);
        acc = f4fma(w.y, h4tof4(sb[(i01 << 2) + j]), acc);
        acc = f4fma(w.z, h4tof4(sb[(i10 << 2) + j]), acc);
        acc = f4fma(w.w, h4tof4(sb[(i11 << 2) + j]), acc);
    }
    return f4scale(1.0f / den, acc);
}

// ---------------- K2: fine deform  (n1 -> a1) ----------------
__global__ void __launch_bounds__(TB)
k2_fine(const float* __restrict__ dww, const float* __restrict__ dwb,
        const float* __restrict__ pww, const float* __restrict__ pwb) {
    __shared__ float s_dww[144], s_dwb[16], s_pwb[75];
    __shared__ float4 s_pw4[75 * 5];
    __shared__ float4 s_tap[TB / 4][25];
    __shared__ unsigned s_idx[TB / 4][25];
    int tid = threadIdx.x;
    ldblk(s_dww, dww, 144, tid);
    ldblk(s_dwb, dwb, 16, tid);
    ldblk(s_pwb, pwb, 75, tid);
    ldpad((float*)s_pw4, pww, 75, tid);
    __syncthreads();

    int g = tid >> 2, j = tid & 3;
    int lane = tid & 31;
    int p = tile_pixel(blockIdx.x, g);
    int b = p >> 16, y = (p >> 8) & 255, x = p & 255;
    const uint2* sb = gh_n1 + ((size_t)b << 18);
    float4 o = deform_core4(sb, y, x, lane, j, s_dww, s_dwb, s_pw4, s_pwb,
                            1.0f, 4.0f, &s_tap[g][0], &s_idx[g][0]);
    gh_a1[(size_t)p * 4 + j] = f4toh4(o);
}

// ---------------- K3: coarse deform + rmsnorm + gate + proj_out + sigma ----------------
__global__ void __launch_bounds__(TB)
k3_coarse_tail(const float* __restrict__ dww, const float* __restrict__ dwb,
               const float* __restrict__ pww, const float* __restrict__ pwb,
               const float* __restrict__ n2w,
               const float* __restrict__ gate_w, const float* __restrict__ gate_b,
               const float* __restrict__ pout_w, const float* __restrict__ pout_b,
               const float* __restrict__ sig_w, const float* __restrict__ sig_b) {
    __shared__ float s_dww[144], s_dwb[16], s_pwb[75], s_n2w[16], s_sigb[3];
    __shared__ float4 s_pw4[75 * 5];
    __shared__ float4 s_gT4[16 * 5], s_pT4[16 * 5];
    __shared__ float4 s_gb4[4], s_pb4[4], s_sig4[12];
    __shared__ float4 s_tap[TB / 4][25];
    __shared__ unsigned s_idx[TB / 4][25];
    int tid = threadIdx.x;
    ldblk(s_dww, dww, 144, tid);
    ldblk(s_dwb, dwb, 16, tid);
    ldblk(s_pwb, pwb, 75, tid);
    ldpad((float*)s_pw4, pww, 75, tid);
    ldtpad((float*)s_gT4, gate_w, tid);
    ldtpad((float*)s_pT4, pout_w, tid);
    ldblk((float*)s_gb4, gate_b, 16, tid);
    ldblk((float*)s_pb4, pout_b, 16, tid);
    ldblk((float*)s_sig4, sig_w, 48, tid);
    ldblk(s_n2w, n2w, 16, tid);
    ldblk(s_sigb, sig_b, 3, tid);
    __syncthreads();

    int g = tid >> 2, j = tid & 3;
    int lane = tid & 31;
    int p = tile_pixel(blockIdx.x, g);
    int b = p >> 16, y = (p >> 8) & 255, x = p & 255;
    const int c0 = 4 * j;
    const uint2* sb = gh_a1 + ((size_t)b << 18);

    float4 av = deform_core4(sb, y, x, lane, j, s_dww, s_dwb, s_pw4, s_pwb,
                             3.0f, 6.0f, &s_tap[g][0], &s_idx[g][0]);

    // rmsnorm(a2, norm2)
    float ssp = av.x * av.x + av.y * av.y + av.z * av.z + av.w * av.w;
    float ss = rsum4(ssp);
    float inv = 1.0f / (sqrtf(ss) * 0.25f + EPSF);
    float4 tv = make_float4(av.x * inv * s_n2w[c0], av.y * inv * s_n2w[c0 + 1],
                            av.z * inv * s_n2w[c0 + 2], av.w * inv * s_n2w[c0 + 3]);

    float4 tf[4];
    bcast16v(tv, lane, tf);

    float4 a3 = s_gb4[j];
#pragma unroll
    for (int r = 0; r < 4; r++) {
        a3 = f4fma(tf[r].x, s_gT4[(4 * r + 0) * 5 + j], a3);
        a3 = f4fma(tf[r].y, s_gT4[(4 * r + 1) * 5 + j], a3);
        a3 = f4fma(tf[r].z, s_gT4[(4 * r + 2) * 5 + j], a3);
        a3 = f4fma(tf[r].w, s_gT4[(4 * r + 3) * 5 + j], a3);
    }
    float4 f0v = g4_feat0[(size_t)p * 4 + j];
    float4 gv = make_float4(f0v.x * a3.x, f0v.y * a3.y, f0v.z * a3.z, f0v.w * a3.w);

    float4 gf[4];
    bcast16v(gv, lane, gf);

    float4 fv = f4add(s_pb4[j], g4_short[(size_t)p * 4 + j]);
#pragma unroll
    for (int r = 0; r < 4; r++) {
        fv = f4fma(gf[r].x, s_pT4[(4 * r + 0) * 5 + j], fv);
        fv = f4fma(gf[r].y, s_pT4[(4 * r + 1) * 5 + j], fv);
        fv = f4fma(gf[r].z, s_pT4[(4 * r + 2) * 5 + j], fv);
        fv = f4fma(gf[r].w, s_pT4[(4 * r + 3) * 5 + j], fv);
    }
    g4_feat[(size_t)p * 4 + j] = fv;
    gh_feat[(size_t)p * 4 + j] = f4toh4(fv);

    float sg[3];
#pragma unroll
    for (int r = 0; r < 3; r++) {
        float zp = dot44(fv, s_sig4[r * 4 + j]);
        float z = rsum4(zp) + s_sigb[r];
        float sp = fmaxf(z, 0.0f) + log1pf(expf(-fabsf(z)));
        sg[r] = fminf(sp, 6.0f) + EPSF;
    }
    if (j == 0) g_sig[p] = make_float4(sg[0], sg[1], sg[2], 0.0f);
}

// ---------------- K4: joint bilateral (R8 tap layout) ----------------
__global__ void __launch_bounds__(TB)
k4_bilateral(const float* __restrict__ xin,
             const float* __restrict__ offw, const float* __restrict__ offb,
             float* __restrict__ out) {
    __shared__ float4 s_ow4[50 * 5];
    __shared__ float s_ob[50];
    __shared__ float4 s_tap[TB / 4][25];
    __shared__ float s_aux[TB / 4][25];   // spat
    int tid = threadIdx.x;
    ldpad((float*)s_ow4, offw, 50, tid);
    ldblk(s_ob, offb, 50, tid);
    __syncthreads();

    int g = tid >> 2, j = tid & 3;
    int lane = tid & 31;
    int p = tile_pixel(blockIdx.x, g);
    int b = p >> 16, y = (p >> 8) & 255, x = p & 255;

    float4 fv = g4_feat[(size_t)p * 4 + j];
    float4 fvv[4];
    bcast16v(fv, lane, fvv);

    float4 s4 = g_sig[p];
    float axc = 0.5f / (s4.x * s4.x);
    float ayc = 0.5f / (s4.y * s4.y);
    float arc = 0.5f / (s4.z * s4.z);

    const float* plane = xin + (size_t)b * 4 * HW;
    const uint2* fb = gh_feat + ((size_t)b << 18);
    float4* tap_s = &s_tap[g][0];
    float* aux_s = &s_aux[g][0];

    // phase 1: lane j owns k = j, j+4, ... (compute only)
    for (int k = j; k < 25; k += 4) {
        const float4* wx4 = s_ow4 + (2 * k) * 5;
        const float4* wy4 = s_ow4 + (2 * k + 1) * 5;
        float px = s_ob[2 * k], py = s_ob[2 * k + 1];
#pragma unroll
        for (int q = 0; q < 4; q++) {
            px += dot44(fvv[q], wx4[q]);
            py += dot44(fvv[q], wy4[q]);
        }
        float dx = (float)((k % 5) - 2) + tanh_p(px) * 5.0f;
        float dy = (float)((k / 5) - 2) + tanh_p(py) * 5.0f;
        float spat = dx * dx * axc + dy * dy * ayc;
        TapPack tp = mk_tap_pack((float)x + dx, (float)y + dy);
        tap_s[k] = make_float4(__uint_as_float(tp.ua), __uint_as_float(tp.ub),
                               tp.wx, tp.wy);
        aux_s[k] = spat;
    }
    __syncwarp();

    // phase 2: feat gather (half) + corner-split patch; patch reduce deferred
    float num = 0.0f, den = 0.0f;
#pragma unroll 2
    for (int k = 0; k < 25; k++) {
        float4 tp = tap_s[k];
        float spat = aux_s[k];
        unsigned ua = __float_as_uint(tp.x), ub = __float_as_uint(tp.y);
        int i00 = ua & 0xffff, i01 = ua >> 16, i10 = ub & 0xffff, i11 = ub >> 16;
        float wx = tp.z, wy = tp.w;
        float omx = 1.0f - wx, omy = 1.0f - wy;
        float w00 = omx * omy, w01 = wx * omy, w10 = omx * wy, w11 = wx * wy;

        float4 s = f4scale(w00, h4tof4(fb[(i00 << 2) + j]));
        s = f4fma(w01, h4tof4(fb[(i01 << 2) + j]), s);
        s = f4fma(w10, h4tof4(fb[(i10 << 2) + j]), s);
        s = f4fma(w11, h4tof4(fb[(i11 << 2) + j]), s);
        float ddx = fv.x - s.x, ddy = fv.y - s.y, ddz = fv.z - s.z, ddw = fv.w - s.w;
        float fdp = ddx * ddx + ddy * ddy + ddz * ddz + ddw * ddw;

        // patch partial: lane j loads its corner only, reduce deferred to end
        int ci = (j & 2) ? ((j & 1) ? i11 : i10) : ((j & 1) ? i01 : i00);
        float cw = (j & 2) ? ((j & 1) ? w11 : w10) : ((j & 1) ? w01 : w00);
        float pp = cw * plane[ci];

        float fd = rsum4(fdp);
        float wgt = __expf(-spat - fd * arc);
        num = fmaf(pp, wgt, num);    // lane-partial numerator
        den += wgt;                  // group-uniform
    }
    num = rsum4(num);
    if (j == 0) out[p] = num / (den + 1e-8f);
}

// ---------------- launch ----------------
extern "C" void kernel_launch(void* const* d_in, const int* in_sizes, int n_in,
                              void* d_out, int out_size) {
    const float* x = (const float*)d_in[0];
    const int NB4 = (NPIX * 4) / TB;   // 2048 blocks = 8x8 tiles

    k1_proj<<<NB4, TB>>>(x, (const float*)d_in[1], (const float*)d_in[2],
                         (const float*)d_in[3], (const float*)d_in[4],
                         (const float*)d_in[5]);
    k2_fine<<<NB4, TB>>>((const float*)d_in[6], (const float*)d_in[7],
                         (const float*)d_in[8], (const float*)d_in[9]);
    k3_coarse_tail<<<NB4, TB>>>((const float*)d_in[10], (const float*)d_in[11],
                                (const float*)d_in[12], (const float*)d_in[13],
                                (const float*)d_in[14],
                                (const float*)d_in[15], (const float*)d_in[16],
                                (const float*)d_in[17], (const float*)d_in[18],
                                (const float*)d_in[19], (const float*)d_in[20]);
    k4_bilateral<<<NB4, TB>>>(x, (const float*)d_in[21], (const float*)d_in[22],
                              (float*)d_out);
}

// round 11
// speedup vs baseline: 1.3963x; 1.0541x over previous
#include <cuda_runtime.h>
#include <cuda_fp16.h>
#include <math.h>

#define NPIX  131072            // B*H*W = 2*256*256
#define HW    65536
#define EPSF  1e-6f
#define TB    256

// ---------------- scratch (static __device__, no allocation) ----------------
__device__ float4 g4_short[NPIX * 4];
__device__ float4 g4_feat0[NPIX * 4];
__device__ float4 g4_feat[NPIX * 4];       // fp32 feat (center reads in k4)
__device__ uint2  gh_n1[NPIX * 4];         // half x4 per lane chunk
__device__ uint2  gh_a1[NPIX * 4];
__device__ uint2  gh_feat[NPIX * 4];
__device__ float4 g_sig[NPIX];             // (sx, sy, sr, -)

// ---------------- helpers ----------------
__device__ __forceinline__ float4 f4fma(float a, float4 b, float4 c) {
    return make_float4(fmaf(a, b.x, c.x), fmaf(a, b.y, c.y),
                       fmaf(a, b.z, c.z), fmaf(a, b.w, c.w));
}
__device__ __forceinline__ float4 f4scale(float a, float4 b) {
    return make_float4(a * b.x, a * b.y, a * b.z, a * b.w);
}
__device__ __forceinline__ float4 f4add(float4 a, float4 b) {
    return make_float4(a.x + b.x, a.y + b.y, a.z + b.z, a.w + b.w);
}
__device__ __forceinline__ float dot44(float4 a, float4 b) {
    return fmaf(a.x, b.x, fmaf(a.y, b.y, fmaf(a.z, b.z, a.w * b.w)));
}
__device__ __forceinline__ float rsum4(float v) {
    v += __shfl_xor_sync(0xffffffffu, v, 1);
    v += __shfl_xor_sync(0xffffffffu, v, 2);
    return v;
}
__device__ __forceinline__ void bcast16v(float4 v, int lane, float4 out[4]) {
    int base = lane & ~3;
#pragma unroll
    for (int q = 0; q < 4; q++) {
        out[q] = make_float4(__shfl_sync(0xffffffffu, v.x, base + q),
                             __shfl_sync(0xffffffffu, v.y, base + q),
                             __shfl_sync(0xffffffffu, v.z, base + q),
                             __shfl_sync(0xffffffffu, v.w, base + q));
    }
}
__device__ __forceinline__ __half2 u2h2(unsigned u) {
    __half2 h;
    *reinterpret_cast<unsigned*>(&h) = u;
    return h;
}
__device__ __forceinline__ unsigned h2u(__half2 h) {
    return *reinterpret_cast<unsigned*>(&h);
}
__device__ __forceinline__ float4 h4tof4(uint2 u) {
    float2 a = __half22float2(u2h2(u.x)), b = __half22float2(u2h2(u.y));
    return make_float4(a.x, a.y, b.x, b.y);
}
__device__ __forceinline__ uint2 f4toh4(float4 v) {
    uint2 u;
    u.x = h2u(__floats2half2_rn(v.x, v.y));
    u.y = h2u(__floats2half2_rn(v.z, v.w));
    return u;
}
__device__ __forceinline__ float geluf(float v) {
    return 0.5f * v * (1.0f + erff(v * 0.7071067811865476f));
}
__device__ __forceinline__ float tanh_p(float x) {
    float ax = fabsf(x);
    float e = __expf(2.0f * ax);
    float t = 1.0f - 2.0f / (e + 1.0f);
    return copysignf(t, x);
}
// valid for |c| < 510 (always true here: |offset| <= 12, x in [0,255])
__device__ __forceinline__ float reflectf(float c) {
    float a = fabsf(c);
    return a > 255.0f ? 510.0f - a : a;
}
__device__ __forceinline__ int reflecti(int i) {
    i = abs(i);
    return i > 255 ? 510 - i : i;
}
// ---- deform tap: single packed idx + half2-packed weights (pre-scaled by e)
__device__ __forceinline__ uint4 mk_tap_h(float ix, float iy, float e) {
    ix = reflectf(ix);
    iy = reflectf(iy);
    float fx = floorf(ix), fy = floorf(iy);
    float wx = ix - fx, wy = iy - fy;
    int x0 = (int)fx, y0 = (int)fy;
    unsigned u = (unsigned)((y0 << 8) + x0);
    if (x0 < 255) u |= 1u << 16;
    if (y0 < 255) u |= 1u << 17;
    float omx = 1.0f - wx, omy = 1.0f - wy;
    float omye = omy * e, wye = wy * e;
    uint4 t;
    t.x = u;
    t.y = h2u(__floats2half2_rn(omx * omye, wx * omye));
    t.z = h2u(__floats2half2_rn(omx * wye, wx * wye));
    t.w = 0;
    return t;
}
__device__ __forceinline__ void unpack_tap(unsigned u, int& i00, int& i01, int& i10, int& i11) {
    i00 = u & 0xffff;
    int sx = (u >> 16) & 1;
    i01 = i00 + sx;
    i10 = i00 + ((u >> 9) & 0x100);
    i11 = i10 + sx;
}
// ---- k4 tap: explicit packed index pairs + half weights
__device__ __forceinline__ uint4 mk_tap_k4(float ix, float iy) {
    ix = reflectf(ix);
    iy = reflectf(iy);
    float fx = floorf(ix), fy = floorf(iy);
    float wx = ix - fx, wy = iy - fy;
    int x0 = (int)fx, y0 = (int)fy;
    int x1 = min(x0 + 1, 255), y1 = min(y0 + 1, 255);
    int r0 = y0 << 8, r1 = y1 << 8;
    float omx = 1.0f - wx, omy = 1.0f - wy;
    uint4 t;
    t.x = (unsigned)(r0 + x0) | ((unsigned)(r0 + x1) << 16);
    t.y = (unsigned)(r1 + x0) | ((unsigned)(r1 + x1) << 16);
    t.z = h2u(__floats2half2_rn(omx * omy, wx * omy));
    t.w = h2u(__floats2half2_rn(omx * wy, wx * wy));
    return t;
}

// half2 bilinear blend of one uint (2 channels) across 4 corners
__device__ __forceinline__ __half2 hblend(unsigned v00, unsigned v01, unsigned v10, unsigned v11,
                                          __half2 w00b, __half2 w01b, __half2 w10b, __half2 w11b) {
    __half2 a = __hmul2(w00b, u2h2(v00));
    a = __hfma2(w01b, u2h2(v01), a);
    a = __hfma2(w10b, u2h2(v10), a);
    a = __hfma2(w11b, u2h2(v11), a);
    return a;
}

// 8x8 tile mapping: block -> (batch, tile-y, tile-x); group g in block -> pixel
__device__ __forceinline__ int tile_pixel(int bi, int g) {
    int b = bi >> 10;
    int ty = (bi >> 5) & 31;
    int tx = bi & 31;
    int y = (ty << 3) + (g >> 3);
    int x = (tx << 3) + (g & 7);
    return (b << 16) | (y << 8) | x;
}

// ---------------- smem loaders (TB threads) ----------------
__device__ __forceinline__ void ldblk(float* dst, const float* src, int n, int tid) {
    for (int i = tid; i < n; i += TB) dst[i] = src[i];
}
__device__ __forceinline__ void ldpad(float* dst, const float* src, int rows, int tid) {
    for (int i = tid; i < rows * 16; i += TB) {
        int r = i >> 4, c = i & 15;
        dst[r * 20 + c] = src[i];
    }
}
__device__ __forceinline__ void ldtpad(float* dst, const float* src, int tid) {
    for (int i = tid; i < 256; i += TB) {
        int o = i >> 4, c = i & 15;
        dst[c * 20 + o] = src[i];
    }
}

// ---------------- K1: proj + gelu + rmsnorm (4 lanes / pixel) ----------------
__global__ void __launch_bounds__(TB)
k1_proj(const float* __restrict__ x,
        const float* __restrict__ pm_w, const float* __restrict__ pm_b,
        const float* __restrict__ pa_w, const float* __restrict__ pa_b,
        const float* __restrict__ n1w) {
    int tid = threadIdx.x;
    int p = tile_pixel(blockIdx.x, tid >> 2);
    int j = tid & 3;
    int b = p >> 16;
    int hw = p & 0xFFFF;
    const float* xb = x + (size_t)b * 4 * HW;
    float x0 = xb[hw], x1 = xb[HW + hw], x2 = xb[2 * HW + hw], x3 = xb[3 * HW + hw];

    int c0 = 4 * j;
    float sc[4], f0[4];
    float ssp = 0.0f;
#pragma unroll
    for (int q = 0; q < 4; q++) {
        int c = c0 + q;
        float v = pm_w[c] * x0 + pm_b[c] + pa_b[c]
                + pa_w[c * 3 + 0] * x1 + pa_w[c * 3 + 1] * x2 + pa_w[c * 3 + 2] * x3;
        sc[q] = v;
        float g = geluf(v);
        f0[q] = g;
        ssp += g * g;
    }
    float ss = rsum4(ssp);
    float inv = 1.0f / (sqrtf(ss) * 0.25f + EPSF);

    g4_short[(size_t)p * 4 + j] = make_float4(sc[0], sc[1], sc[2], sc[3]);
    g4_feat0[(size_t)p * 4 + j] = make_float4(f0[0], f0[1], f0[2], f0[3]);
    gh_n1[(size_t)p * 4 + j] = f4toh4(make_float4(f0[0] * inv * n1w[c0],
                                                  f0[1] * inv * n1w[c0 + 1],
                                                  f0[2] * inv * n1w[c0 + 2],
                                                  f0[3] * inv * n1w[c0 + 3]));
}

// ---------------- deform core: half2 blend, weights+den finished in phase 1 ----
__device__ __forceinline__ float4 deform_core4(
    const uint2* __restrict__ sb, int y, int x, int lane, int j,
    const float* s_dww, const float* s_dwb,
    const float4* s_pw4, const float* s_pwb,
    float spacing, float mo, uint4* tap_s)
{
    const int c0 = 4 * j;

    // depthwise 3x3 (reflect) + bias, channel-split
    float4 h = make_float4(s_dwb[c0], s_dwb[c0 + 1], s_dwb[c0 + 2], s_dwb[c0 + 3]);
#pragma unroll
    for (int ky = 0; ky < 3; ky++) {
        int yy = reflecti(y + ky - 1);
#pragma unroll
        for (int kx = 0; kx < 3; kx++) {
            int xx = reflecti(x + kx - 1);
            float4 v = h4tof4(sb[(((yy << 8) + xx) << 2) + j]);
            const float* wb = s_dww + ky * 3 + kx;
            h.x = fmaf(v.x, wb[(c0 + 0) * 9], h.x);
            h.y = fmaf(v.y, wb[(c0 + 1) * 9], h.y);
            h.z = fmaf(v.z, wb[(c0 + 2) * 9], h.z);
            h.w = fmaf(v.w, wb[(c0 + 3) * 9], h.w);
        }
    }
    h.x = geluf(h.x); h.y = geluf(h.y); h.z = geluf(h.z); h.w = geluf(h.w);

    float4 hv[4];
    bcast16v(h, lane, hv);

    // phase 1: lane j owns k = j, j+4, ...  (weights pre-scaled by e; den here)
    float denp = 0.0f;
    for (int k = j; k < 25; k += 4) {
        const float4* wx4 = s_pw4 + (2 * k) * 5;
        const float4* wy4 = s_pw4 + (2 * k + 1) * 5;
        const float4* wl4 = s_pw4 + (50 + k) * 5;
        float px = s_pwb[2 * k], py = s_pwb[2 * k + 1], pl = s_pwb[50 + k];
#pragma unroll
        for (int q = 0; q < 4; q++) {
            px += dot44(hv[q], wx4[q]);
            py += dot44(hv[q], wy4[q]);
            pl += dot44(hv[q], wl4[q]);
        }
        float dx = spacing * (float)((k % 5) - 2) + tanh_p(px) * mo;
        float dy = spacing * (float)((k / 5) - 2) + tanh_p(py) * mo;
        float e = __expf(pl);
        denp += e;
        tap_s[k] = mk_tap_h((float)x + dx, (float)y + dy, e);
    }
    __syncwarp();
    float den = rsum4(denp);

    // phase 2: half2 blend, fp32 accumulate
    float4 acc = make_float4(0.f, 0.f, 0.f, 0.f);
#pragma unroll 2
    for (int k = 0; k < 25; k++) {
        uint4 t = tap_s[k];
        int i00, i01, i10, i11;
        unpack_tap(t.x, i00, i01, i10, i11);
        __half2 w0 = u2h2(t.y), w1 = u2h2(t.z);
        __half2 w00b = __low2half2(w0), w01b = __high2half2(w0);
        __half2 w10b = __low2half2(w1), w11b = __high2half2(w1);
        uint2 v00 = sb[(i00 << 2) + j], v01 = sb[(i01 << 2) + j];
        uint2 v10 = sb[(i10 << 2) + j], v11 = sb[(i11 << 2) + j];
        __half2 a0 = hblend(v00.x, v01.x, v10.x, v11.x, w00b, w01b, w10b, w11b);
        __half2 a1 = hblend(v00.y, v01.y, v10.y, v11.y, w00b, w01b, w10b, w11b);
        float2 f0 = __half22float2(a0), f1 = __half22float2(a1);
        acc.x += f0.x; acc.y += f0.y; acc.z += f1.x; acc.w += f1.y;
    }
    return f4scale(1.0f / den, acc);
}

// ---------------- K2: fine deform  (n1 -> a1) ----------------
__global__ void __launch_bounds__(TB)
k2_fine(const float* __restrict__ dww, const float* __restrict__ dwb,
        const float* __restrict__ pww, const float* __restrict__ pwb) {
    __shared__ float s_dww[144], s_dwb[16], s_pwb[75];
    __shared__ float4 s_pw4[75 * 5];
    __shared__ uint4 s_tap[TB / 4][25];
    int tid = threadIdx.x;
    ldblk(s_dww, dww, 144, tid);
    ldblk(s_dwb, dwb, 16, tid);
    ldblk(s_pwb, pwb, 75, tid);
    ldpad((float*)s_pw4, pww, 75, tid);
    __syncthreads();

    int g = tid >> 2, j = tid & 3;
    int lane = tid & 31;
    int p = tile_pixel(blockIdx.x, g);
    int b = p >> 16, y = (p >> 8) & 255, x = p & 255;
    const uint2* sb = gh_n1 + ((size_t)b << 18);
    float4 o = deform_core4(sb, y, x, lane, j, s_dww, s_dwb, s_pw4, s_pwb,
                            1.0f, 4.0f, &s_tap[g][0]);
    gh_a1[(size_t)p * 4 + j] = f4toh4(o);
}

// ---------------- K3: coarse deform + rmsnorm + gate + proj_out + sigma ----------------
__global__ void __launch_bounds__(TB)
k3_coarse_tail(const float* __restrict__ dww, const float* __restrict__ dwb,
               const float* __restrict__ pww, const float* __restrict__ pwb,
               const float* __restrict__ n2w,
               const float* __restrict__ gate_w, const float* __restrict__ gate_b,
               const float* __restrict__ pout_w, const float* __restrict__ pout_b,
               const float* __restrict__ sig_w, const float* __restrict__ sig_b) {
    __shared__ float s_dww[144], s_dwb[16], s_pwb[75], s_n2w[16], s_sigb[3];
    __shared__ float4 s_pw4[75 * 5];
    __shared__ float4 s_gT4[16 * 5], s_pT4[16 * 5];
    __shared__ float4 s_gb4[4], s_pb4[4], s_sig4[12];
    __shared__ uint4 s_tap[TB / 4][25];
    int tid = threadIdx.x;
    ldblk(s_dww, dww, 144, tid);
    ldblk(s_dwb, dwb, 16, tid);
    ldblk(s_pwb, pwb, 75, tid);
    ldpad((float*)s_pw4, pww, 75, tid);
    ldtpad((float*)s_gT4, gate_w, tid);
    ldtpad((float*)s_pT4, pout_w, tid);
    ldblk((float*)s_gb4, gate_b, 16, tid);
    ldblk((float*)s_pb4, pout_b, 16, tid);
    ldblk((float*)s_sig4, sig_w, 48, tid);
    ldblk(s_n2w, n2w, 16, tid);
    ldblk(s_sigb, sig_b, 3, tid);
    __syncthreads();

    int g = tid >> 2, j = tid & 3;
    int lane = tid & 31;
    int p = tile_pixel(blockIdx.x, g);
    int b = p >> 16, y = (p >> 8) & 255, x = p & 255;
    const int c0 = 4 * j;
    const uint2* sb = gh_a1 + ((size_t)b << 18);

    float4 av = deform_core4(sb, y, x, lane, j, s_dww, s_dwb, s_pw4, s_pwb,
                             3.0f, 6.0f, &s_tap[g][0]);

    // rmsnorm(a2, norm2)
    float ssp = av.x * av.x + av.y * av.y + av.z * av.z + av.w * av.w;
    float ss = rsum4(ssp);
    float inv = 1.0f / (sqrtf(ss) * 0.25f + EPSF);
    float4 tv = make_float4(av.x * inv * s_n2w[c0], av.y * inv * s_n2w[c0 + 1],
                            av.z * inv * s_n2w[c0 + 2], av.w * inv * s_n2w[c0 + 3]);

    float4 tf[4];
    bcast16v(tv, lane, tf);

    float4 a3 = s_gb4[j];
#pragma unroll
    for (int r = 0; r < 4; r++) {
        a3 = f4fma(tf[r].x, s_gT4[(4 * r + 0) * 5 + j], a3);
        a3 = f4fma(tf[r].y, s_gT4[(4 * r + 1) * 5 + j], a3);
        a3 = f4fma(tf[r].z, s_gT4[(4 * r + 2) * 5 + j], a3);
        a3 = f4fma(tf[r].w, s_gT4[(4 * r + 3) * 5 + j], a3);
    }
    float4 f0v = g4_feat0[(size_t)p * 4 + j];
    float4 gv = make_float4(f0v.x * a3.x, f0v.y * a3.y, f0v.z * a3.z, f0v.w * a3.w);

    float4 gf[4];
    bcast16v(gv, lane, gf);

    float4 fv = f4add(s_pb4[j], g4_short[(size_t)p * 4 + j]);
#pragma unroll
    for (int r = 0; r < 4; r++) {
        fv = f4fma(gf[r].x, s_pT4[(4 * r + 0) * 5 + j], fv);
        fv = f4fma(gf[r].y, s_pT4[(4 * r + 1) * 5 + j], fv);
        fv = f4fma(gf[r].z, s_pT4[(4 * r + 2) * 5 + j], fv);
        fv = f4fma(gf[r].w, s_pT4[(4 * r + 3) * 5 + j], fv);
    }
    g4_feat[(size_t)p * 4 + j] = fv;
    gh_feat[(size_t)p * 4 + j] = f4toh4(fv);

    float sg[3];
#pragma unroll
    for (int r = 0; r < 3; r++) {
        float zp = dot44(fv, s_sig4[r * 4 + j]);
        float z = rsum4(zp) + s_sigb[r];
        float sp = fmaxf(z, 0.0f) + log1pf(expf(-fabsf(z)));
        sg[r] = fminf(sp, 6.0f) + EPSF;
    }
    if (j == 0) g_sig[p] = make_float4(sg[0], sg[1], sg[2], 0.0f);
}

// ---------------- K4: joint bilateral ----------------
__global__ void __launch_bounds__(TB)
k4_bilateral(const float* __restrict__ xin,
             const float* __restrict__ offw, const float* __restrict__ offb,
             float* __restrict__ out) {
    __shared__ float4 s_ow4[50 * 5];
    __shared__ float s_ob[50];
    __shared__ uint4 s_tap[TB / 4][25];
    __shared__ float s_aux[TB / 4][25];   // spat
    int tid = threadIdx.x;
    ldpad((float*)s_ow4, offw, 50, tid);
    ldblk(s_ob, offb, 50, tid);
    __syncthreads();

    int g = tid >> 2, j = tid & 3;
    int lane = tid & 31;
    int p = tile_pixel(blockIdx.x, g);
    int b = p >> 16, y = (p >> 8) & 255, x = p & 255;

    float4 fv = g4_feat[(size_t)p * 4 + j];
    float4 fvv[4];
    bcast16v(fv, lane, fvv);

    float4 s4 = g_sig[p];
    float axc = 0.5f / (s4.x * s4.x);
    float ayc = 0.5f / (s4.y * s4.y);
    float arc = 0.5f / (s4.z * s4.z);

    const float* plane = xin + (size_t)b * 4 * HW;
    const uint2* fb = gh_feat + ((size_t)b << 18);
    uint4* tap_s = &s_tap[g][0];
    float* aux_s = &s_aux[g][0];

    // phase 1: lane j owns k = j, j+4, ... (compute only)
    for (int k = j; k < 25; k += 4) {
        const float4* wx4 = s_ow4 + (2 * k) * 5;
        const float4* wy4 = s_ow4 + (2 * k + 1) * 5;
        float px = s_ob[2 * k], py = s_ob[2 * k + 1];
#pragma unroll
        for (int q = 0; q < 4; q++) {
            px += dot44(fvv[q], wx4[q]);
            py += dot44(fvv[q], wy4[q]);
        }
        float dx = (float)((k % 5) - 2) + tanh_p(px) * 5.0f;
        float dy = (float)((k / 5) - 2) + tanh_p(py) * 5.0f;
        float spat = dx * dx * axc + dy * dy * ayc;
        tap_s[k] = mk_tap_k4((float)x + dx, (float)y + dy);
        aux_s[k] = spat;
    }
    __syncwarp();

    // phase 2: half2 feat blend + corner-split patch; patch reduce deferred
    float num = 0.0f, den = 0.0f;
#pragma unroll 2
    for (int k = 0; k < 25; k++) {
        uint4 t = tap_s[k];
        float spat = aux_s[k];
        int i00 = t.x & 0xffff, i01 = t.x >> 16, i10 = t.y & 0xffff, i11 = t.y >> 16;
        __half2 w0 = u2h2(t.z), w1 = u2h2(t.w);
        __half2 w00b = __low2half2(w0), w01b = __high2half2(w0);
        __half2 w10b = __low2half2(w1), w11b = __high2half2(w1);

        uint2 v00 = fb[(i00 << 2) + j], v01 = fb[(i01 << 2) + j];
        uint2 v10 = fb[(i10 << 2) + j], v11 = fb[(i11 << 2) + j];
        __half2 a0 = hblend(v00.x, v01.x, v10.x, v11.x, w00b, w01b, w10b, w11b);
        __half2 a1 = hblend(v00.y, v01.y, v10.y, v11.y, w00b, w01b, w10b, w11b);
        float2 f0 = __half22float2(a0), f1 = __half22float2(a1);
        float ddx = fv.x - f0.x, ddy = fv.y - f0.y, ddz = fv.z - f1.x, ddw = fv.w - f1.y;
        float fdp = ddx * ddx + ddy * ddy + ddz * ddz + ddw * ddw;

        // patch partial: lane j loads its corner only, weight from packed halves
        int ci = (j & 2) ? ((j & 1) ? i11 : i10) : ((j & 1) ? i01 : i00);
        __half2 selw = (j & 2) ? w1 : w0;
        float cw = __half2float((j & 1) ? __high2half(selw) : __low2half(selw));
        float pp = cw * plane[ci];

        float fd = rsum4(fdp);
        float wgt = __expf(-spat - fd * arc);
        num = fmaf(pp, wgt, num);    // lane-partial numerator
        den += wgt;                  // group-uniform
    }
    num = rsum4(num);
    if (j == 0) out[p] = num / (den + 1e-8f);
}

// ---------------- launch ----------------
extern "C" void kernel_launch(void* const* d_in, const int* in_sizes, int n_in,
                              void* d_out, int out_size) {
    const float* x = (const float*)d_in[0];
    const int NB4 = (NPIX * 4) / TB;   // 2048 blocks = 8x8 tiles

    k1_proj<<<NB4, TB>>>(x, (const float*)d_in[1], (const float*)d_in[2],
                         (const float*)d_in[3], (const float*)d_in[4],
                         (const float*)d_in[5]);
    k2_fine<<<NB4, TB>>>((const float*)d_in[6], (const float*)d_in[7],
                         (const float*)d_in[8], (const float*)d_in[9]);
    k3_coarse_tail<<<NB4, TB>>>((const float*)d_in[10], (const float*)d_in[11],
                                (const float*)d_in[12], (const float*)d_in[13],
                                (const float*)d_in[14],
                                (const float*)d_in[15], (const float*)d_in[16],
                                (const float*)d_in[17], (const float*)d_in[18],
                                (const float*)d_in[19], (const float*)d_in[20]);
    k4_bilateral<<<NB4, TB>>>(x, (const float*)d_in[21], (const float*)d_in[22],
                              (float*)d_out);
}